// round 2
// baseline (speedup 1.0000x reference)
#include <cuda_runtime.h>
#include <cuda_bf16.h>
#include <math.h>

// Problem constants
#define TOKENS   4096          // B*S = 2*2048
#define HIDDEN_  2048
#define NHEADS   16
#define NKV      2
#define HDIM     256
#define QDIM     4096          // NHEADS*HDIM
#define KVDIM    512           // NKV*HDIM
#define QGDIM    8192          // NHEADS*HDIM*2  (FIXED: was 16384)
#define ROT      64
#define SCALE    0.0625f       // 1/sqrt(256)

// ---------------- scratch (allocation-free: __device__ globals) ----------------
__device__ float g_Q[(size_t)TOKENS * QDIM];      // 67 MB  (normalized+roped in place)
__device__ float g_Gate[(size_t)TOKENS * QDIM];   // 67 MB
__device__ float g_K[(size_t)TOKENS * KVDIM];     // 8 MB
__device__ float g_V[(size_t)TOKENS * KVDIM];     // 8 MB
__device__ float g_Attn[(size_t)TOKENS * QDIM];   // 67 MB  (gated attention out)

// ---------------- SGEMM: C[M,N] = A[M,K] * B[N,K]^T  (both row-major, NT) ------
// mode 0: C0[r*N+c] = v
// mode 1: QG split: col c -> head h=c>>9, w=c&511; w<256 -> C0 (Q), else C1 (gate)
#define BM 128
#define BN 128
#define BK 16

__global__ void __launch_bounds__(256) sgemm_nt(
    const float* __restrict__ A, const float* __restrict__ B,
    float* __restrict__ C0, float* __restrict__ C1,
    int M, int N, int K, int mode)
{
    __shared__ float As[BK][BM];
    __shared__ float Bs[BK][BN];
    const int tid = threadIdx.x;
    const int rowBase = blockIdx.y * BM;
    const int colBase = blockIdx.x * BN;
    const int tr = (tid >> 4) << 3;   // 0..120
    const int tc = (tid & 15) << 3;   // 0..120

    // loader mapping: 512 float4 per tile per matrix, 2 per thread
    const int ar0 = tid >> 2;             const int ak0 = (tid & 3) << 2;
    const int l1  = tid + 256;
    const int ar1 = l1 >> 2;              const int ak1 = (l1 & 3) << 2;

    const float* Aptr0 = A + (size_t)(rowBase + ar0) * K + ak0;
    const float* Aptr1 = A + (size_t)(rowBase + ar1) * K + ak1;
    const float* Bptr0 = B + (size_t)(colBase + ar0) * K + ak0;
    const float* Bptr1 = B + (size_t)(colBase + ar1) * K + ak1;

    float acc[8][8];
#pragma unroll
    for (int i = 0; i < 8; i++)
#pragma unroll
        for (int j = 0; j < 8; j++) acc[i][j] = 0.f;

    float4 ra0 = *(const float4*)Aptr0;
    float4 ra1 = *(const float4*)Aptr1;
    float4 rb0 = *(const float4*)Bptr0;
    float4 rb1 = *(const float4*)Bptr1;

    const int KT = K / BK;
    for (int kt = 0; kt < KT; kt++) {
        As[ak0+0][ar0] = ra0.x; As[ak0+1][ar0] = ra0.y; As[ak0+2][ar0] = ra0.z; As[ak0+3][ar0] = ra0.w;
        As[ak1+0][ar1] = ra1.x; As[ak1+1][ar1] = ra1.y; As[ak1+2][ar1] = ra1.z; As[ak1+3][ar1] = ra1.w;
        Bs[ak0+0][ar0] = rb0.x; Bs[ak0+1][ar0] = rb0.y; Bs[ak0+2][ar0] = rb0.z; Bs[ak0+3][ar0] = rb0.w;
        Bs[ak1+0][ar1] = rb1.x; Bs[ak1+1][ar1] = rb1.y; Bs[ak1+2][ar1] = rb1.z; Bs[ak1+3][ar1] = rb1.w;
        __syncthreads();

        if (kt + 1 < KT) {   // prefetch next tile while computing
            const int koff = (kt + 1) * BK;
            ra0 = *(const float4*)(Aptr0 + koff);
            ra1 = *(const float4*)(Aptr1 + koff);
            rb0 = *(const float4*)(Bptr0 + koff);
            rb1 = *(const float4*)(Bptr1 + koff);
        }

#pragma unroll
        for (int k = 0; k < BK; k++) {
            float a[8], b[8];
#pragma unroll
            for (int i = 0; i < 8; i++) a[i] = As[k][tr + i];
#pragma unroll
            for (int j = 0; j < 8; j++) b[j] = Bs[k][tc + j];
#pragma unroll
            for (int i = 0; i < 8; i++)
#pragma unroll
                for (int j = 0; j < 8; j++) acc[i][j] += a[i] * b[j];
        }
        __syncthreads();
    }

    if (mode == 0) {
#pragma unroll
        for (int i = 0; i < 8; i++) {
            float* cp = C0 + (size_t)(rowBase + tr + i) * N + colBase + tc;
            *(float4*)(cp)     = make_float4(acc[i][0], acc[i][1], acc[i][2], acc[i][3]);
            *(float4*)(cp + 4) = make_float4(acc[i][4], acc[i][5], acc[i][6], acc[i][7]);
        }
    } else {
        // 8-col chunk never crosses a 256 boundary (tc multiple of 8)
        const int c0 = colBase + tc;
        const int h  = c0 >> 9;
        const int w  = c0 & 511;
        float* base = (w < 256 ? C0 : C1);
#pragma unroll
        for (int i = 0; i < 8; i++) {
            float* cp = base + (size_t)(rowBase + tr + i) * QDIM + h * HDIM + (w & 255);
            *(float4*)(cp)     = make_float4(acc[i][0], acc[i][1], acc[i][2], acc[i][3]);
            *(float4*)(cp + 4) = make_float4(acc[i][4], acc[i][5], acc[i][6], acc[i][7]);
        }
    }
}

// ---------------- fused RMSNorm (over 256) + partial RoPE (first 64 dims) ------
// grid (TOKENS, nheads), block 256; X row stride = nheads*256, normalized in place
__global__ void __launch_bounds__(256) rmsnorm_rope(
    float* __restrict__ X, const float* __restrict__ w,
    const float* __restrict__ cosb, const float* __restrict__ sinb, int stride)
{
    const int t = blockIdx.x;
    const int h = blockIdx.y;
    const int d = threadIdx.x;
    float* xp = X + (size_t)t * stride + h * HDIM;
    float x = xp[d];

    // block sum of squares
    float ss = x * x;
#pragma unroll
    for (int off = 16; off; off >>= 1) ss += __shfl_xor_sync(0xffffffffu, ss, off);
    __shared__ float red[8];
    if ((d & 31) == 0) red[d >> 5] = ss;
    __syncthreads();
    float sum = red[0] + red[1] + red[2] + red[3] + red[4] + red[5] + red[6] + red[7];
    float inv = rsqrtf(sum * (1.f / 256.f) + 1e-6f);
    float n = x * inv * w[d];

    __shared__ float sn[ROT];
    if (d < ROT) sn[d] = n;
    __syncthreads();

    float out = n;
    if (d < 32) {
        float c = cosb[t * ROT + d], s = sinb[t * ROT + d];
        out = n * c - sn[d + 32] * s;
    } else if (d < ROT) {
        float c = cosb[t * ROT + d], s = sinb[t * ROT + d];
        out = n * c + sn[d - 32] * s;
    }
    xp[d] = out;
}

// ---------------- flash attention (causal, online softmax) + sigmoid gate ------
// grid (32 = b*16+h, 256 qblocks of 8), block 256 (8 warps, 1 query row / warp)
#define KTILE 16
__global__ void __launch_bounds__(256) flash_attn(
    const float* __restrict__ Q, const float* __restrict__ Kb,
    const float* __restrict__ Vb, const float* __restrict__ Gate,
    float* __restrict__ O)
{
    const int bh = blockIdx.x;
    const int b  = bh >> 4;
    const int h  = bh & 15;
    const int kvh = h >> 3;
    const int warp = threadIdx.x >> 5;
    const int lane = threadIdx.x & 31;
    const int q = blockIdx.y * 8 + warp;
    const int tq = b * 2048 + q;

    __shared__ float Ks[KTILE][HDIM];
    __shared__ float Vs[KTILE][HDIM];

    float qr[8];
    const float* qp = Q + (size_t)tq * QDIM + h * HDIM + lane * 8;
#pragma unroll
    for (int i = 0; i < 8; i++) qr[i] = qp[i] * SCALE;

    float m = -1e30f, l = 0.f;
    float o[8];
#pragma unroll
    for (int i = 0; i < 8; i++) o[i] = 0.f;

    const int qmax = blockIdx.y * 8 + 7;
    for (int j0 = 0; j0 <= qmax; j0 += KTILE) {
        __syncthreads();
        // cooperative tile load: KTILE*256 floats each of K and V (float4 granularity)
        for (int tt = threadIdx.x; tt < KTILE * (HDIM / 4); tt += 256) {
            const int r  = tt >> 6;     // HDIM/4 = 64 float4 per row
            const int c4 = tt & 63;
            const size_t src = (size_t)(b * 2048 + j0 + r) * KVDIM + kvh * HDIM;
            ((float4*)Ks[r])[c4] = ((const float4*)(Kb + src))[c4];
            ((float4*)Vs[r])[c4] = ((const float4*)(Vb + src))[c4];
        }
        __syncthreads();

        const int jend = min(KTILE - 1, q - j0);
        for (int jj = 0; jj <= jend; jj++) {
            const float* kr = Ks[jj] + lane * 8;
            float s = 0.f;
#pragma unroll
            for (int i = 0; i < 8; i++) s += qr[i] * kr[i];
#pragma unroll
            for (int off = 16; off; off >>= 1) s += __shfl_xor_sync(0xffffffffu, s, off);

            float nm   = fmaxf(m, s);
            float corr = __expf(m - nm);
            float p    = __expf(s - nm);
            l = l * corr + p;
            m = nm;
            const float* vr = Vs[jj] + lane * 8;
#pragma unroll
            for (int i = 0; i < 8; i++) o[i] = o[i] * corr + p * vr[i];
        }
    }

    const float invl = 1.f / l;
    const float* gp = Gate + (size_t)tq * QDIM + h * HDIM + lane * 8;
    float* op = O + (size_t)tq * QDIM + h * HDIM + lane * 8;
#pragma unroll
    for (int i = 0; i < 8; i++) {
        float g   = gp[i];
        float sig = 1.f / (1.f + __expf(-g));
        op[i] = o[i] * invl * sig;
    }
}

// ---------------- launcher ------------------------------------------------------
extern "C" void kernel_launch(void* const* d_in, const int* in_sizes, int n_in,
                              void* d_out, int out_size)
{
    const float* hidden = (const float*)d_in[0];
    const float* cosb   = (const float*)d_in[1];
    const float* sinb   = (const float*)d_in[2];
    const float* Wq     = (const float*)d_in[3];
    const float* Wk     = (const float*)d_in[4];
    const float* Wv     = (const float*)d_in[5];
    const float* Wo     = (const float*)d_in[6];
    const float* qnw    = (const float*)d_in[7];
    const float* knw    = (const float*)d_in[8];
    float* out = (float*)d_out;

    float *Qb, *Gb, *Kb, *Vb, *Ab;
    cudaGetSymbolAddress((void**)&Qb, g_Q);
    cudaGetSymbolAddress((void**)&Gb, g_Gate);
    cudaGetSymbolAddress((void**)&Kb, g_K);
    cudaGetSymbolAddress((void**)&Vb, g_V);
    cudaGetSymbolAddress((void**)&Ab, g_Attn);

    // 1) QG projection (fused Q/gate de-interleave)
    sgemm_nt<<<dim3(QGDIM / BN, TOKENS / BM), 256>>>(hidden, Wq, Qb, Gb,
                                                     TOKENS, QGDIM, HIDDEN_, 1);
    // 2,3) K and V projections
    sgemm_nt<<<dim3(KVDIM / BN, TOKENS / BM), 256>>>(hidden, Wk, Kb, nullptr,
                                                     TOKENS, KVDIM, HIDDEN_, 0);
    sgemm_nt<<<dim3(KVDIM / BN, TOKENS / BM), 256>>>(hidden, Wv, Vb, nullptr,
                                                     TOKENS, KVDIM, HIDDEN_, 0);
    // 4) RMSNorm + RoPE (in place)
    rmsnorm_rope<<<dim3(TOKENS, NHEADS), 256>>>(Qb, qnw, cosb, sinb, QDIM);
    rmsnorm_rope<<<dim3(TOKENS, NKV),    256>>>(Kb, knw, cosb, sinb, KVDIM);
    // 5) causal flash attention + sigmoid gate
    flash_attn<<<dim3(32, 2048 / 8), 256>>>(Qb, Kb, Vb, Gb, Ab);
    // 6) output projection
    sgemm_nt<<<dim3(HIDDEN_ / BN, TOKENS / BM), 256>>>(Ab, Wo, out, nullptr,
                                                       TOKENS, HIDDEN_, QDIM, 0);
}

// round 7
// speedup vs baseline: 1.3248x; 1.3248x over previous
#include <cuda_runtime.h>
#include <cuda_bf16.h>
#include <math.h>
#include <stdint.h>

// Problem constants
#define TOKENS   4096          // B*S = 2*2048
#define HIDDEN_  2048
#define NHEADS   16
#define NKV      2
#define HDIM     256
#define QDIM     4096          // NHEADS*HDIM
#define KVDIM    512           // NKV*HDIM
#define QGDIM    8192          // NHEADS*HDIM*2
#define ROT      64
#define SCALE    0.0625f       // 1/sqrt(256)

// ---------------- scratch (allocation-free: __device__ globals) ----------------
__device__ float g_Q[(size_t)TOKENS * QDIM];      // normalized+roped in place
__device__ float g_Gate[(size_t)TOKENS * QDIM];
__device__ float g_K[(size_t)TOKENS * KVDIM];
__device__ float g_V[(size_t)TOKENS * KVDIM];

// bf16 hi/lo split operands for HMMA GEMMs
__device__ __nv_bfloat16 g_hid_hi[(size_t)TOKENS * HIDDEN_];
__device__ __nv_bfloat16 g_hid_lo[(size_t)TOKENS * HIDDEN_];
__device__ __nv_bfloat16 g_Wq_hi[(size_t)QGDIM * HIDDEN_];
__device__ __nv_bfloat16 g_Wq_lo[(size_t)QGDIM * HIDDEN_];
__device__ __nv_bfloat16 g_Wk_hi[(size_t)KVDIM * HIDDEN_];
__device__ __nv_bfloat16 g_Wk_lo[(size_t)KVDIM * HIDDEN_];
__device__ __nv_bfloat16 g_Wv_hi[(size_t)KVDIM * HIDDEN_];
__device__ __nv_bfloat16 g_Wv_lo[(size_t)KVDIM * HIDDEN_];
__device__ __nv_bfloat16 g_Wo_hi[(size_t)HIDDEN_ * QDIM];
__device__ __nv_bfloat16 g_Wo_lo[(size_t)HIDDEN_ * QDIM];
__device__ __nv_bfloat16 g_Attn_hi[(size_t)TOKENS * QDIM];
__device__ __nv_bfloat16 g_Attn_lo[(size_t)TOKENS * QDIM];

// =================== baseline-ISA helpers (no sm_103a features) ===================
__device__ __forceinline__ uint32_t smem_u32(const void* p) {
    uint32_t a;
    asm("{ .reg .u64 t; cvta.to.shared.u64 t, %1; cvt.u32.u64 %0, t; }" : "=r"(a) : "l"(p));
    return a;
}
__device__ __forceinline__ void cp16(uint32_t s, const void* g) {
    asm volatile("cp.async.cg.shared.global [%0], [%1], 16;" :: "r"(s), "l"(g));
}
#define CP_COMMIT() asm volatile("cp.async.commit_group;" ::: "memory")
#define CP_WAIT(n)  asm volatile("cp.async.wait_group %0;" :: "n"(n) : "memory")

__device__ __forceinline__ void ldsm4(uint32_t& r0, uint32_t& r1, uint32_t& r2, uint32_t& r3,
                                      uint32_t addr) {
    asm volatile("ldmatrix.sync.aligned.m8n8.x4.shared.b16 {%0,%1,%2,%3}, [%4];"
        : "=r"(r0), "=r"(r1), "=r"(r2), "=r"(r3) : "r"(addr));
}
__device__ __forceinline__ void mma16816(float* d, const uint32_t* a, uint32_t b0, uint32_t b1) {
    asm volatile("mma.sync.aligned.m16n8k16.row.col.f32.bf16.bf16.f32 "
        "{%0,%1,%2,%3}, {%4,%5,%6,%7}, {%8,%9}, {%0,%1,%2,%3};"
        : "+f"(d[0]), "+f"(d[1]), "+f"(d[2]), "+f"(d[3])
        : "r"(a[0]), "r"(a[1]), "r"(a[2]), "r"(a[3]), "r"(b0), "r"(b1));
}

// =================== bf16 hi/lo split kernel ===================
__device__ __forceinline__ void sp1(float x, __nv_bfloat16& h, __nv_bfloat16& l) {
    h = __float2bfloat16(x);
    l = __float2bfloat16(x - __bfloat162float(h));
}
__global__ void __launch_bounds__(256) split_bf16(
    const float* __restrict__ X, __nv_bfloat16* __restrict__ H,
    __nv_bfloat16* __restrict__ L, int n4)
{
    int i = blockIdx.x * 256 + threadIdx.x;
    if (i >= n4) return;
    float4 x = ((const float4*)X)[i];
    __nv_bfloat16 h0,h1,h2,h3,l0,l1,l2,l3;
    sp1(x.x,h0,l0); sp1(x.y,h1,l1); sp1(x.z,h2,l2); sp1(x.w,h3,l3);
    __nv_bfloat162* H2 = (__nv_bfloat162*)H;
    __nv_bfloat162* L2 = (__nv_bfloat162*)L;
    H2[i*2]   = __nv_bfloat162(h0,h1);
    H2[i*2+1] = __nv_bfloat162(h2,h3);
    L2[i*2]   = __nv_bfloat162(l0,l1);
    L2[i*2+1] = __nv_bfloat162(l2,l3);
}

// =================== HMMA 3-term bf16-split GEMM ===================
// C[M,N] = A[M,K] * B[N,K]^T.  Block tile 128x128, BK=32, cp.async double buffer.
// Warp grid 2(m) x 4(n): warp tile 64x32.  mma m16n8k16, 3 terms (hh, hl, lh).
// mode 0: C0[m*N+c];  mode 1: QG de-interleave -> C0 (Q) / C1 (gate), head-major.
#define GBK    32
#define ROWB   80                 // smem bytes per row: 32 bf16 + 8 pad (conflict-free)
#define TILEB  (128 * ROWB)       // 10240
#define STAGEB (4 * TILEB)        // 40960: Ahi, Alo, Bhi, Blo
#define GSMEM  (2 * STAGEB)       // 81920

__device__ __forceinline__ void load_stage(
    uint32_t sbase, const __nv_bfloat16* __restrict__ Ahi, const __nv_bfloat16* __restrict__ Alo,
    const __nv_bfloat16* __restrict__ Bhi, const __nv_bfloat16* __restrict__ Blo,
    int rowBase, int colBase, int K, int k0, int tid)
{
    // 4 tiles x 512 chunks(16B); per thread 8 chunks; tile index = i>>1 (constant per i)
#pragma unroll
    for (int i = 0; i < 8; i++) {
        const int t   = i >> 1;                    // 0:Ahi 1:Alo 2:Bhi 3:Blo
        const int idx = ((i & 1) << 8) + tid;      // 0..511
        const int r   = idx >> 2;
        const int c   = idx & 3;
        const __nv_bfloat16* src = (t == 0) ? Ahi : (t == 1) ? Alo : (t == 2) ? Bhi : Blo;
        const int base = (t < 2) ? rowBase : colBase;
        cp16(sbase + t * TILEB + r * ROWB + c * 16,
             src + (size_t)(base + r) * K + k0 + c * 8);
    }
}

__global__ void __launch_bounds__(256, 1) gemm_hmma(
    const __nv_bfloat16* __restrict__ Ahi, const __nv_bfloat16* __restrict__ Alo,
    const __nv_bfloat16* __restrict__ Bhi, const __nv_bfloat16* __restrict__ Blo,
    float* __restrict__ C0, float* __restrict__ C1,
    int K, int N, int mode)
{
    extern __shared__ char smem[];
    const uint32_t sbase = smem_u32(smem);
    const int tid  = threadIdx.x;
    const int w    = tid >> 5;
    const int lane = tid & 31;
    const int rowBase = blockIdx.y * 128;
    const int colBase = blockIdx.x * 128;
    const int wm = (w & 1) * 64;       // warp m offset
    const int wn = (w >> 1) * 32;      // warp n offset

    float acc[4][4][4];
#pragma unroll
    for (int mi = 0; mi < 4; mi++)
#pragma unroll
        for (int nj = 0; nj < 4; nj++)
#pragma unroll
            for (int e = 0; e < 4; e++) acc[mi][nj][e] = 0.f;

    // ldmatrix lane addressing (within a tile, given k-step byte offset kb):
    //   A m-tile: row = wm + mi*16 + (lane&15), kseg = (lane>>4)&1
    //   B n-pair: n   = wn + pi*16 + (lane&7) + ((lane>>4)&1)*8, kseg = (lane>>3)&1
    const uint32_t aRowOff = (uint32_t)(wm + (lane & 15)) * ROWB + ((lane >> 4) & 1) * 16;
    const uint32_t bRowOff = (uint32_t)(wn + (lane & 7) + ((lane >> 4) & 1) * 8) * ROWB
                           + ((lane >> 3) & 1) * 16;

    const int KT = K / GBK;
    load_stage(sbase, Ahi, Alo, Bhi, Blo, rowBase, colBase, K, 0, tid);
    CP_COMMIT();

    for (int kt = 0; kt < KT; kt++) {
        if (kt + 1 < KT) {
            load_stage(sbase + ((kt + 1) & 1) * STAGEB, Ahi, Alo, Bhi, Blo,
                       rowBase, colBase, K, (kt + 1) * GBK, tid);
            CP_COMMIT();
            CP_WAIT(1);
        } else {
            CP_WAIT(0);
        }
        __syncthreads();

        const uint32_t st = sbase + (kt & 1) * STAGEB;
#pragma unroll
        for (int s = 0; s < 2; s++) {              // two k16 steps in BK=32
            const uint32_t kb = s * 32;
            uint32_t ah[4][4], al[4][4], bh[2][4], bl[2][4];
#pragma unroll
            for (int mi = 0; mi < 4; mi++) {
                const uint32_t off = aRowOff + (uint32_t)mi * 16 * ROWB + kb;
                ldsm4(ah[mi][0], ah[mi][1], ah[mi][2], ah[mi][3], st + 0 * TILEB + off);
                ldsm4(al[mi][0], al[mi][1], al[mi][2], al[mi][3], st + 1 * TILEB + off);
            }
#pragma unroll
            for (int pi = 0; pi < 2; pi++) {
                const uint32_t off = bRowOff + (uint32_t)pi * 16 * ROWB + kb;
                ldsm4(bh[pi][0], bh[pi][1], bh[pi][2], bh[pi][3], st + 2 * TILEB + off);
                ldsm4(bl[pi][0], bl[pi][1], bl[pi][2], bl[pi][3], st + 3 * TILEB + off);
            }
#pragma unroll
            for (int mi = 0; mi < 4; mi++)
#pragma unroll
                for (int pi = 0; pi < 2; pi++)
#pragma unroll
                    for (int hf = 0; hf < 2; hf++) {
                        const int nj = pi * 2 + hf;
                        const uint32_t b0h = bh[pi][hf * 2], b1h = bh[pi][hf * 2 + 1];
                        const uint32_t b0l = bl[pi][hf * 2], b1l = bl[pi][hf * 2 + 1];
                        mma16816(acc[mi][nj], ah[mi], b0h, b1h);   // hi*hi
                        mma16816(acc[mi][nj], ah[mi], b0l, b1l);   // hi*lo
                        mma16816(acc[mi][nj], al[mi], b0h, b1h);   // lo*hi
                    }
        }
        __syncthreads();
    }

    // epilogue: lane holds rows (r, r+8), col pair (c, c+1) per mma tile
    const int lr = lane >> 2;
    const int lc = (lane & 3) * 2;
#pragma unroll
    for (int mi = 0; mi < 4; mi++) {
#pragma unroll
        for (int nj = 0; nj < 4; nj++) {
            const int r0 = rowBase + wm + mi * 16 + lr;
            const int cg = colBase + wn + nj * 8 + lc;
            const float2 v0 = make_float2(acc[mi][nj][0], acc[mi][nj][1]);
            const float2 v1 = make_float2(acc[mi][nj][2], acc[mi][nj][3]);
            if (mode == 0) {
                *(float2*)(C0 + (size_t)r0 * N + cg)       = v0;
                *(float2*)(C0 + (size_t)(r0 + 8) * N + cg) = v1;
            } else {
                const int h = cg >> 9, ww = cg & 511;
                float* base = (ww < 256) ? C0 : C1;
                const int col = h * HDIM + (ww & 255);
                *(float2*)(base + (size_t)r0 * QDIM + col)       = v0;
                *(float2*)(base + (size_t)(r0 + 8) * QDIM + col) = v1;
            }
        }
    }
}

// ---------------- fused RMSNorm (over 256) + partial RoPE (first 64 dims) ------
__global__ void __launch_bounds__(256) rmsnorm_rope(
    float* __restrict__ X, const float* __restrict__ w,
    const float* __restrict__ cosb, const float* __restrict__ sinb, int stride)
{
    const int t = blockIdx.x;
    const int h = blockIdx.y;
    const int d = threadIdx.x;
    float* xp = X + (size_t)t * stride + h * HDIM;
    float x = xp[d];

    float ss = x * x;
#pragma unroll
    for (int off = 16; off; off >>= 1) ss += __shfl_xor_sync(0xffffffffu, ss, off);
    __shared__ float red[8];
    if ((d & 31) == 0) red[d >> 5] = ss;
    __syncthreads();
    float sum = red[0] + red[1] + red[2] + red[3] + red[4] + red[5] + red[6] + red[7];
    float inv = rsqrtf(sum * (1.f / 256.f) + 1e-6f);
    float n = x * inv * w[d];

    __shared__ float sn[ROT];
    if (d < ROT) sn[d] = n;
    __syncthreads();

    float out = n;
    if (d < 32) {
        float c = cosb[t * ROT + d], s = sinb[t * ROT + d];
        out = n * c - sn[d + 32] * s;
    } else if (d < ROT) {
        float c = cosb[t * ROT + d], s = sinb[t * ROT + d];
        out = n * c + sn[d - 32] * s;
    }
    xp[d] = out;
}

// ---------------- flash attention (causal, online softmax) + sigmoid gate ------
// epilogue writes gated output as bf16 hi/lo (feeds Wo HMMA GEMM)
#define KTILE 16
__global__ void __launch_bounds__(256) flash_attn(
    const float* __restrict__ Q, const float* __restrict__ Kb,
    const float* __restrict__ Vb, const float* __restrict__ Gate,
    __nv_bfloat16* __restrict__ Ohi, __nv_bfloat16* __restrict__ Olo)
{
    const int bh = blockIdx.x;
    const int b  = bh >> 4;
    const int h  = bh & 15;
    const int kvh = h >> 3;
    const int warp = threadIdx.x >> 5;
    const int lane = threadIdx.x & 31;
    const int q = blockIdx.y * 8 + warp;
    const int tq = b * 2048 + q;

    __shared__ float Ks[KTILE][HDIM];
    __shared__ float Vs[KTILE][HDIM];

    float qr[8];
    const float* qp = Q + (size_t)tq * QDIM + h * HDIM + lane * 8;
#pragma unroll
    for (int i = 0; i < 8; i++) qr[i] = qp[i] * SCALE;

    float m = -1e30f, l = 0.f;
    float o[8];
#pragma unroll
    for (int i = 0; i < 8; i++) o[i] = 0.f;

    const int qmax = blockIdx.y * 8 + 7;
    for (int j0 = 0; j0 <= qmax; j0 += KTILE) {
        __syncthreads();
        for (int tt = threadIdx.x; tt < KTILE * (HDIM / 4); tt += 256) {
            const int r  = tt >> 6;
            const int c4 = tt & 63;
            const size_t src = (size_t)(b * 2048 + j0 + r) * KVDIM + kvh * HDIM;
            ((float4*)Ks[r])[c4] = ((const float4*)(Kb + src))[c4];
            ((float4*)Vs[r])[c4] = ((const float4*)(Vb + src))[c4];
        }
        __syncthreads();

        const int jend = min(KTILE - 1, q - j0);
        for (int jj = 0; jj <= jend; jj++) {
            const float* kr = Ks[jj] + lane * 8;
            float s = 0.f;
#pragma unroll
            for (int i = 0; i < 8; i++) s += qr[i] * kr[i];
#pragma unroll
            for (int off = 16; off; off >>= 1) s += __shfl_xor_sync(0xffffffffu, s, off);

            float nm   = fmaxf(m, s);
            float corr = __expf(m - nm);
            float p    = __expf(s - nm);
            l = l * corr + p;
            m = nm;
            const float* vr = Vs[jj] + lane * 8;
#pragma unroll
            for (int i = 0; i < 8; i++) o[i] = o[i] * corr + p * vr[i];
        }
    }

    const float invl = 1.f / l;
    const float* gp = Gate + (size_t)tq * QDIM + h * HDIM + lane * 8;
    const size_t ob = (size_t)tq * QDIM + h * HDIM + lane * 8;
#pragma unroll
    for (int i = 0; i < 8; i++) {
        float g   = gp[i];
        float sig = 1.f / (1.f + __expf(-g));
        float val = o[i] * invl * sig;
        __nv_bfloat16 hi = __float2bfloat16(val);
        Ohi[ob + i] = hi;
        Olo[ob + i] = __float2bfloat16(val - __bfloat162float(hi));
    }
}

// ---------------- launcher ------------------------------------------------------
extern "C" void kernel_launch(void* const* d_in, const int* in_sizes, int n_in,
                              void* d_out, int out_size)
{
    const float* hidden = (const float*)d_in[0];
    const float* cosb   = (const float*)d_in[1];
    const float* sinb   = (const float*)d_in[2];
    const float* Wq     = (const float*)d_in[3];
    const float* Wk     = (const float*)d_in[4];
    const float* Wv     = (const float*)d_in[5];
    const float* Wo     = (const float*)d_in[6];
    const float* qnw    = (const float*)d_in[7];
    const float* knw    = (const float*)d_in[8];
    float* out = (float*)d_out;

    float *Qb, *Gb, *Kb, *Vb;
    cudaGetSymbolAddress((void**)&Qb, g_Q);
    cudaGetSymbolAddress((void**)&Gb, g_Gate);
    cudaGetSymbolAddress((void**)&Kb, g_K);
    cudaGetSymbolAddress((void**)&Vb, g_V);
    __nv_bfloat16 *hidH,*hidL,*WqH,*WqL,*WkH,*WkL,*WvH,*WvL,*WoH,*WoL,*AtH,*AtL;
    cudaGetSymbolAddress((void**)&hidH, g_hid_hi);  cudaGetSymbolAddress((void**)&hidL, g_hid_lo);
    cudaGetSymbolAddress((void**)&WqH,  g_Wq_hi);   cudaGetSymbolAddress((void**)&WqL,  g_Wq_lo);
    cudaGetSymbolAddress((void**)&WkH,  g_Wk_hi);   cudaGetSymbolAddress((void**)&WkL,  g_Wk_lo);
    cudaGetSymbolAddress((void**)&WvH,  g_Wv_hi);   cudaGetSymbolAddress((void**)&WvL,  g_Wv_lo);
    cudaGetSymbolAddress((void**)&WoH,  g_Wo_hi);   cudaGetSymbolAddress((void**)&WoL,  g_Wo_lo);
    cudaGetSymbolAddress((void**)&AtH,  g_Attn_hi); cudaGetSymbolAddress((void**)&AtL,  g_Attn_lo);

    cudaFuncSetAttribute(gemm_hmma, cudaFuncAttributeMaxDynamicSharedMemorySize, GSMEM);

    // 0) split fp32 -> bf16 hi/lo
    {
        int n;
        n = TOKENS * HIDDEN_ / 4;  split_bf16<<<(n+255)/256, 256>>>(hidden, hidH, hidL, n);
        n = QGDIM  * HIDDEN_ / 4;  split_bf16<<<(n+255)/256, 256>>>(Wq, WqH, WqL, n);
        n = KVDIM  * HIDDEN_ / 4;  split_bf16<<<(n+255)/256, 256>>>(Wk, WkH, WkL, n);
        n = KVDIM  * HIDDEN_ / 4;  split_bf16<<<(n+255)/256, 256>>>(Wv, WvH, WvL, n);
        n = HIDDEN_ * QDIM  / 4;   split_bf16<<<(n+255)/256, 256>>>(Wo, WoH, WoL, n);
    }

    // 1) QG projection (fused Q/gate de-interleave), HMMA
    gemm_hmma<<<dim3(QGDIM/128, TOKENS/128), 256, GSMEM>>>(
        hidH, hidL, WqH, WqL, Qb, Gb, HIDDEN_, QGDIM, 1);
    // 2,3) K and V projections
    gemm_hmma<<<dim3(KVDIM/128, TOKENS/128), 256, GSMEM>>>(
        hidH, hidL, WkH, WkL, Kb, nullptr, HIDDEN_, KVDIM, 0);
    gemm_hmma<<<dim3(KVDIM/128, TOKENS/128), 256, GSMEM>>>(
        hidH, hidL, WvH, WvL, Vb, nullptr, HIDDEN_, KVDIM, 0);
    // 4) RMSNorm + RoPE (in place)
    rmsnorm_rope<<<dim3(TOKENS, NHEADS), 256>>>(Qb, qnw, cosb, sinb, QDIM);
    rmsnorm_rope<<<dim3(TOKENS, NKV),    256>>>(Kb, knw, cosb, sinb, KVDIM);
    // 5) causal flash attention + sigmoid gate (writes bf16 hi/lo)
    flash_attn<<<dim3(32, 2048 / 8), 256>>>(Qb, Kb, Vb, Gb, AtH, AtL);
    // 6) output projection, HMMA
    gemm_hmma<<<dim3(HIDDEN_/128, TOKENS/128), 256, GSMEM>>>(
        AtH, AtL, WoH, WoL, out, nullptr, QDIM, HIDDEN_, 0);
}

// round 10
// speedup vs baseline: 4.9890x; 3.7657x over previous
#include <cuda_runtime.h>
#include <cuda_bf16.h>
#include <math.h>
#include <stdint.h>

// Problem constants
#define TOKENS   4096          // B*S = 2*2048
#define HIDDEN_  2048
#define NHEADS   16
#define NKV      2
#define HDIM     256
#define QDIM     4096          // NHEADS*HDIM
#define KVDIM    512           // NKV*HDIM
#define QGDIM    8192          // NHEADS*HDIM*2
#define ROT      64
#define SCALE    0.0625f       // 1/sqrt(256)
#define K2EXP    0.09016844f   // SCALE * log2(e)

// ---------------- scratch (allocation-free: __device__ globals) ----------------
__device__ float g_Q[(size_t)TOKENS * QDIM];      // raw QG output (pre-norm)
__device__ float g_Gate[(size_t)TOKENS * QDIM];
__device__ float g_K[(size_t)TOKENS * KVDIM];
__device__ float g_V[(size_t)TOKENS * KVDIM];

// bf16 hi/lo split operands
__device__ __nv_bfloat16 g_hid_hi[(size_t)TOKENS * HIDDEN_];
__device__ __nv_bfloat16 g_hid_lo[(size_t)TOKENS * HIDDEN_];
__device__ __nv_bfloat16 g_Wq_hi[(size_t)QGDIM * HIDDEN_];
__device__ __nv_bfloat16 g_Wq_lo[(size_t)QGDIM * HIDDEN_];
__device__ __nv_bfloat16 g_Wk_hi[(size_t)KVDIM * HIDDEN_];
__device__ __nv_bfloat16 g_Wk_lo[(size_t)KVDIM * HIDDEN_];
__device__ __nv_bfloat16 g_Wv_hi[(size_t)KVDIM * HIDDEN_];
__device__ __nv_bfloat16 g_Wv_lo[(size_t)KVDIM * HIDDEN_];
__device__ __nv_bfloat16 g_Wo_hi[(size_t)HIDDEN_ * QDIM];
__device__ __nv_bfloat16 g_Wo_lo[(size_t)HIDDEN_ * QDIM];
__device__ __nv_bfloat16 g_Attn_hi[(size_t)TOKENS * QDIM];
__device__ __nv_bfloat16 g_Attn_lo[(size_t)TOKENS * QDIM];
// normalized+roped Q/K and V as bf16 hi/lo for HMMA flash
__device__ __nv_bfloat16 g_Qhi[(size_t)TOKENS * QDIM];
__device__ __nv_bfloat16 g_Qlo[(size_t)TOKENS * QDIM];
__device__ __nv_bfloat16 g_Khi[(size_t)TOKENS * KVDIM];
__device__ __nv_bfloat16 g_Klo[(size_t)TOKENS * KVDIM];
__device__ __nv_bfloat16 g_Vhi[(size_t)TOKENS * KVDIM];
__device__ __nv_bfloat16 g_Vlo[(size_t)TOKENS * KVDIM];

// =================== baseline-ISA helpers ===================
__device__ __forceinline__ uint32_t smem_u32(const void* p) {
    uint32_t a;
    asm("{ .reg .u64 t; cvta.to.shared.u64 t, %1; cvt.u32.u64 %0, t; }" : "=r"(a) : "l"(p));
    return a;
}
__device__ __forceinline__ void cp16(uint32_t s, const void* g) {
    asm volatile("cp.async.cg.shared.global [%0], [%1], 16;" :: "r"(s), "l"(g));
}
#define CP_COMMIT() asm volatile("cp.async.commit_group;" ::: "memory")
#define CP_WAIT(n)  asm volatile("cp.async.wait_group %0;" :: "n"(n) : "memory")

__device__ __forceinline__ void ldsm4(uint32_t& r0, uint32_t& r1, uint32_t& r2, uint32_t& r3,
                                      uint32_t addr) {
    asm volatile("ldmatrix.sync.aligned.m8n8.x4.shared.b16 {%0,%1,%2,%3}, [%4];"
        : "=r"(r0), "=r"(r1), "=r"(r2), "=r"(r3) : "r"(addr));
}
__device__ __forceinline__ void ldsm4t(uint32_t& r0, uint32_t& r1, uint32_t& r2, uint32_t& r3,
                                       uint32_t addr) {
    asm volatile("ldmatrix.sync.aligned.m8n8.x4.trans.shared.b16 {%0,%1,%2,%3}, [%4];"
        : "=r"(r0), "=r"(r1), "=r"(r2), "=r"(r3) : "r"(addr));
}
__device__ __forceinline__ void mma16816(float* d, const uint32_t* a, uint32_t b0, uint32_t b1) {
    asm volatile("mma.sync.aligned.m16n8k16.row.col.f32.bf16.bf16.f32 "
        "{%0,%1,%2,%3}, {%4,%5,%6,%7}, {%8,%9}, {%0,%1,%2,%3};"
        : "+f"(d[0]), "+f"(d[1]), "+f"(d[2]), "+f"(d[3])
        : "r"(a[0]), "r"(a[1]), "r"(a[2]), "r"(a[3]), "r"(b0), "r"(b1));
}
__device__ __forceinline__ float ex2(float x) {
    float r; asm("ex2.approx.f32 %0, %1;" : "=f"(r) : "f"(x)); return r;
}
__device__ __forceinline__ float frcp(float x) {
    float r; asm("rcp.approx.f32 %0, %1;" : "=f"(r) : "f"(x)); return r;
}
__device__ __forceinline__ uint32_t pack_bf16(float lo, float hi) {
    uint32_t r;
    asm("cvt.rn.satfinite.bf16x2.f32 %0, %1, %2;" : "=r"(r) : "f"(hi), "f"(lo));
    return r;
}

// =================== bf16 hi/lo split kernel ===================
__device__ __forceinline__ void sp1(float x, __nv_bfloat16& h, __nv_bfloat16& l) {
    h = __float2bfloat16(x);
    l = __float2bfloat16(x - __bfloat162float(h));
}
__global__ void __launch_bounds__(256) split_bf16(
    const float* __restrict__ X, __nv_bfloat16* __restrict__ H,
    __nv_bfloat16* __restrict__ L, int n4)
{
    int i = blockIdx.x * 256 + threadIdx.x;
    if (i >= n4) return;
    float4 x = ((const float4*)X)[i];
    __nv_bfloat16 h0,h1,h2,h3,l0,l1,l2,l3;
    sp1(x.x,h0,l0); sp1(x.y,h1,l1); sp1(x.z,h2,l2); sp1(x.w,h3,l3);
    __nv_bfloat162* H2 = (__nv_bfloat162*)H;
    __nv_bfloat162* L2 = (__nv_bfloat162*)L;
    H2[i*2]   = __nv_bfloat162(h0,h1);
    H2[i*2+1] = __nv_bfloat162(h2,h3);
    L2[i*2]   = __nv_bfloat162(l0,l1);
    L2[i*2+1] = __nv_bfloat162(l2,l3);
}

// =================== HMMA 3-term bf16-split GEMM (unchanged from R7) ============
#define GBK    32
#define ROWB   80
#define TILEB  (128 * ROWB)
#define STAGEB (4 * TILEB)
#define GSMEM  (2 * STAGEB)

__device__ __forceinline__ void load_stage(
    uint32_t sbase, const __nv_bfloat16* __restrict__ Ahi, const __nv_bfloat16* __restrict__ Alo,
    const __nv_bfloat16* __restrict__ Bhi, const __nv_bfloat16* __restrict__ Blo,
    int rowBase, int colBase, int K, int k0, int tid)
{
#pragma unroll
    for (int i = 0; i < 8; i++) {
        const int t   = i >> 1;
        const int idx = ((i & 1) << 8) + tid;
        const int r   = idx >> 2;
        const int c   = idx & 3;
        const __nv_bfloat16* src = (t == 0) ? Ahi : (t == 1) ? Alo : (t == 2) ? Bhi : Blo;
        const int base = (t < 2) ? rowBase : colBase;
        cp16(sbase + t * TILEB + r * ROWB + c * 16,
             src + (size_t)(base + r) * K + k0 + c * 8);
    }
}

__global__ void __launch_bounds__(256, 1) gemm_hmma(
    const __nv_bfloat16* __restrict__ Ahi, const __nv_bfloat16* __restrict__ Alo,
    const __nv_bfloat16* __restrict__ Bhi, const __nv_bfloat16* __restrict__ Blo,
    float* __restrict__ C0, float* __restrict__ C1,
    int K, int N, int mode)
{
    extern __shared__ char smem[];
    const uint32_t sbase = smem_u32(smem);
    const int tid  = threadIdx.x;
    const int w    = tid >> 5;
    const int lane = tid & 31;
    const int rowBase = blockIdx.y * 128;
    const int colBase = blockIdx.x * 128;
    const int wm = (w & 1) * 64;
    const int wn = (w >> 1) * 32;

    float acc[4][4][4];
#pragma unroll
    for (int mi = 0; mi < 4; mi++)
#pragma unroll
        for (int nj = 0; nj < 4; nj++)
#pragma unroll
            for (int e = 0; e < 4; e++) acc[mi][nj][e] = 0.f;

    const uint32_t aRowOff = (uint32_t)(wm + (lane & 15)) * ROWB + ((lane >> 4) & 1) * 16;
    const uint32_t bRowOff = (uint32_t)(wn + (lane & 7) + ((lane >> 4) & 1) * 8) * ROWB
                           + ((lane >> 3) & 1) * 16;

    const int KT = K / GBK;
    load_stage(sbase, Ahi, Alo, Bhi, Blo, rowBase, colBase, K, 0, tid);
    CP_COMMIT();

    for (int kt = 0; kt < KT; kt++) {
        if (kt + 1 < KT) {
            load_stage(sbase + ((kt + 1) & 1) * STAGEB, Ahi, Alo, Bhi, Blo,
                       rowBase, colBase, K, (kt + 1) * GBK, tid);
            CP_COMMIT();
            CP_WAIT(1);
        } else {
            CP_WAIT(0);
        }
        __syncthreads();

        const uint32_t st = sbase + (kt & 1) * STAGEB;
#pragma unroll
        for (int s = 0; s < 2; s++) {
            const uint32_t kb = s * 32;
            uint32_t ah[4][4], al[4][4], bh[2][4], bl[2][4];
#pragma unroll
            for (int mi = 0; mi < 4; mi++) {
                const uint32_t off = aRowOff + (uint32_t)mi * 16 * ROWB + kb;
                ldsm4(ah[mi][0], ah[mi][1], ah[mi][2], ah[mi][3], st + 0 * TILEB + off);
                ldsm4(al[mi][0], al[mi][1], al[mi][2], al[mi][3], st + 1 * TILEB + off);
            }
#pragma unroll
            for (int pi = 0; pi < 2; pi++) {
                const uint32_t off = bRowOff + (uint32_t)pi * 16 * ROWB + kb;
                ldsm4(bh[pi][0], bh[pi][1], bh[pi][2], bh[pi][3], st + 2 * TILEB + off);
                ldsm4(bl[pi][0], bl[pi][1], bl[pi][2], bl[pi][3], st + 3 * TILEB + off);
            }
#pragma unroll
            for (int mi = 0; mi < 4; mi++)
#pragma unroll
                for (int pi = 0; pi < 2; pi++)
#pragma unroll
                    for (int hf = 0; hf < 2; hf++) {
                        const int nj = pi * 2 + hf;
                        const uint32_t b0h = bh[pi][hf * 2], b1h = bh[pi][hf * 2 + 1];
                        const uint32_t b0l = bl[pi][hf * 2], b1l = bl[pi][hf * 2 + 1];
                        mma16816(acc[mi][nj], ah[mi], b0h, b1h);
                        mma16816(acc[mi][nj], ah[mi], b0l, b1l);
                        mma16816(acc[mi][nj], al[mi], b0h, b1h);
                    }
        }
        __syncthreads();
    }

    const int lr = lane >> 2;
    const int lc = (lane & 3) * 2;
#pragma unroll
    for (int mi = 0; mi < 4; mi++) {
#pragma unroll
        for (int nj = 0; nj < 4; nj++) {
            const int r0 = rowBase + wm + mi * 16 + lr;
            const int cg = colBase + wn + nj * 8 + lc;
            const float2 v0 = make_float2(acc[mi][nj][0], acc[mi][nj][1]);
            const float2 v1 = make_float2(acc[mi][nj][2], acc[mi][nj][3]);
            if (mode == 0) {
                *(float2*)(C0 + (size_t)r0 * N + cg)       = v0;
                *(float2*)(C0 + (size_t)(r0 + 8) * N + cg) = v1;
            } else {
                const int h = cg >> 9, ww = cg & 511;
                float* base = (ww < 256) ? C0 : C1;
                const int col = h * HDIM + (ww & 255);
                *(float2*)(base + (size_t)r0 * QDIM + col)       = v0;
                *(float2*)(base + (size_t)(r0 + 8) * QDIM + col) = v1;
            }
        }
    }
}

// ---------------- fused RMSNorm + partial RoPE -> bf16 hi/lo --------------------
__global__ void __launch_bounds__(256) rmsnorm_rope_split(
    const float* __restrict__ X, const float* __restrict__ w,
    const float* __restrict__ cosb, const float* __restrict__ sinb, int stride,
    __nv_bfloat16* __restrict__ H, __nv_bfloat16* __restrict__ L)
{
    const int t = blockIdx.x;
    const int h = blockIdx.y;
    const int d = threadIdx.x;
    const float* xp = X + (size_t)t * stride + h * HDIM;
    float x = xp[d];

    float ss = x * x;
#pragma unroll
    for (int off = 16; off; off >>= 1) ss += __shfl_xor_sync(0xffffffffu, ss, off);
    __shared__ float red[8];
    if ((d & 31) == 0) red[d >> 5] = ss;
    __syncthreads();
    float sum = red[0] + red[1] + red[2] + red[3] + red[4] + red[5] + red[6] + red[7];
    float inv = rsqrtf(sum * (1.f / 256.f) + 1e-6f);
    float n = x * inv * w[d];

    __shared__ float sn[ROT];
    if (d < ROT) sn[d] = n;
    __syncthreads();

    float out = n;
    if (d < 32) {
        float c = cosb[t * ROT + d], s = sinb[t * ROT + d];
        out = n * c - sn[d + 32] * s;
    } else if (d < ROT) {
        float c = cosb[t * ROT + d], s = sinb[t * ROT + d];
        out = n * c + sn[d - 32] * s;
    }
    const size_t idx = (size_t)t * stride + h * HDIM + d;
    __nv_bfloat16 hi = __float2bfloat16(out);
    H[idx] = hi;
    L[idx] = __float2bfloat16(out - __bfloat162float(hi));
}

// =================== HMMA flash attention (causal, GQA-shared K/V) ==============
// Block: (b, kvh, 16 q-positions) x 8 heads. 8 warps; warp w = head kvh*8+w,
// m16 fragment over the 16 q rows. K/V tiles (32 kv x 256d, hi/lo) shared by all
// heads. 3-term bf16 split on QK^T and PV. Online softmax in registers.
#define QROWB  528                       // 256*2B + 16 pad (ldsm conflict-free)
#define FSM_QHI 0
#define FSM_QLO (128 * QROWB)
#define FSM_KHI (256 * QROWB)
#define FSM_KLO (288 * QROWB)
#define FSM_VHI (320 * QROWB)
#define FSM_VLO (352 * QROWB)
#define FSMEM   (384 * QROWB)            // 202752 bytes

__global__ void __launch_bounds__(256, 1) flash_hmma(
    const __nv_bfloat16* __restrict__ Qhi, const __nv_bfloat16* __restrict__ Qlo,
    const __nv_bfloat16* __restrict__ Khi, const __nv_bfloat16* __restrict__ Klo,
    const __nv_bfloat16* __restrict__ Vhi, const __nv_bfloat16* __restrict__ Vlo,
    const float* __restrict__ Gate,
    __nv_bfloat16* __restrict__ Ohi, __nv_bfloat16* __restrict__ Olo)
{
    extern __shared__ char smem[];
    const uint32_t sb = smem_u32(smem);
    const int tid  = threadIdx.x;
    const int warp = tid >> 5;
    const int lane = tid & 31;
    const int qblk = blockIdx.x;
    const int b    = blockIdx.y >> 1;
    const int kvh  = blockIdx.y & 1;
    const int qbase = qblk * 16;
    const int h    = kvh * 8 + warp;

    // ---- load Q tile (8 heads x 16 rows x 256d, hi+lo) ----
    for (int i = tid; i < 4096; i += 256) {
        const int r = i >> 5;        // 0..127 : head = r>>4, qrow = r&15
        const int c = i & 31;        // 16B chunk -> d = c*8
        const size_t src = (size_t)(b * 2048 + qbase + (r & 15)) * QDIM
                         + (kvh * 8 + (r >> 4)) * HDIM + c * 8;
        const uint32_t dst = (uint32_t)r * QROWB + c * 16;
        cp16(sb + FSM_QHI + dst, Qhi + src);
        cp16(sb + FSM_QLO + dst, Qlo + src);
    }
    CP_COMMIT();

    float o[32][4];
#pragma unroll
    for (int nt = 0; nt < 32; nt++)
#pragma unroll
        for (int e = 0; e < 4; e++) o[nt][e] = 0.f;
    float m0 = -1e30f, m1 = -1e30f, l0 = 0.f, l1 = 0.f;

    const int g  = lane >> 2;
    const int cb = (lane & 3) * 2;

    // fragment smem addresses
    const uint32_t qAddrHi = sb + FSM_QHI + (uint32_t)(warp * 16 + (lane & 15)) * QROWB
                           + ((lane >> 4) & 1) * 16;
    const uint32_t qAddrLo = qAddrHi + (FSM_QLO - FSM_QHI);
    const uint32_t kAddr   = sb + FSM_KHI
                           + (uint32_t)((lane & 7) + ((lane >> 4) & 1) * 8) * QROWB
                           + ((lane >> 3) & 1) * 16;
    const uint32_t vAddr   = sb + FSM_VHI + (uint32_t)(lane & 15) * QROWB + (lane >> 4) * 16;

    const int ntiles = ((qbase + 15) >> 5) + 1;
    CP_WAIT(0);
    __syncthreads();

    for (int it = 0; it < ntiles; it++) {
        const int j0 = it * 32;
        // ---- load K/V tile (32 x 256, hi/lo x2) ----
        for (int i = tid; i < 1024; i += 256) {
            const int r = i >> 5, c = i & 31;
            const int kr = min(j0 + r, 2047);
            const size_t src = (size_t)(b * 2048 + kr) * KVDIM + kvh * HDIM + c * 8;
            const uint32_t dst = (uint32_t)r * QROWB + c * 16;
            cp16(sb + FSM_KHI + dst, Khi + src);
            cp16(sb + FSM_KLO + dst, Klo + src);
            cp16(sb + FSM_VHI + dst, Vhi + src);
            cp16(sb + FSM_VLO + dst, Vlo + src);
        }
        CP_COMMIT(); CP_WAIT(0);
        __syncthreads();

        // ---- S = Q K^T (16 x 32), 3-term ----
        float S[4][4];
#pragma unroll
        for (int nt = 0; nt < 4; nt++)
#pragma unroll
            for (int e = 0; e < 4; e++) S[nt][e] = 0.f;

#pragma unroll
        for (int ks = 0; ks < 16; ks++) {
            uint32_t qh[4], ql[4], k0h[4], k1h[4], k0l[4], k1l[4];
            ldsm4(qh[0], qh[1], qh[2], qh[3], qAddrHi + ks * 32);
            ldsm4(ql[0], ql[1], ql[2], ql[3], qAddrLo + ks * 32);
            ldsm4(k0h[0], k0h[1], k0h[2], k0h[3], kAddr + ks * 32);
            ldsm4(k1h[0], k1h[1], k1h[2], k1h[3], kAddr + 16 * QROWB + ks * 32);
            ldsm4(k0l[0], k0l[1], k0l[2], k0l[3], kAddr + (FSM_KLO - FSM_KHI) + ks * 32);
            ldsm4(k1l[0], k1l[1], k1l[2], k1l[3], kAddr + (FSM_KLO - FSM_KHI) + 16 * QROWB + ks * 32);
            mma16816(S[0], qh, k0h[0], k0h[1]);
            mma16816(S[0], qh, k0l[0], k0l[1]);
            mma16816(S[0], ql, k0h[0], k0h[1]);
            mma16816(S[1], qh, k0h[2], k0h[3]);
            mma16816(S[1], qh, k0l[2], k0l[3]);
            mma16816(S[1], ql, k0h[2], k0h[3]);
            mma16816(S[2], qh, k1h[0], k1h[1]);
            mma16816(S[2], qh, k1l[0], k1l[1]);
            mma16816(S[2], ql, k1h[0], k1h[1]);
            mma16816(S[3], qh, k1h[2], k1h[3]);
            mma16816(S[3], qh, k1l[2], k1l[3]);
            mma16816(S[3], ql, k1h[2], k1h[3]);
        }

        // ---- causal mask (diagonal tile only) ----
        if (it == ntiles - 1) {
#pragma unroll
            for (int nt = 0; nt < 4; nt++)
#pragma unroll
                for (int e = 0; e < 4; e++) {
                    const int row = qbase + g + (e >> 1) * 8;
                    const int col = j0 + nt * 8 + cb + (e & 1);
                    if (col > row) S[nt][e] = -1e30f;
                }
        }

        // ---- online softmax ----
        float tm0 = -1e30f, tm1 = -1e30f;
#pragma unroll
        for (int nt = 0; nt < 4; nt++) {
            tm0 = fmaxf(tm0, fmaxf(S[nt][0], S[nt][1]));
            tm1 = fmaxf(tm1, fmaxf(S[nt][2], S[nt][3]));
        }
        tm0 = fmaxf(tm0, __shfl_xor_sync(0xffffffffu, tm0, 1));
        tm0 = fmaxf(tm0, __shfl_xor_sync(0xffffffffu, tm0, 2));
        tm1 = fmaxf(tm1, __shfl_xor_sync(0xffffffffu, tm1, 1));
        tm1 = fmaxf(tm1, __shfl_xor_sync(0xffffffffu, tm1, 2));
        const float nm0 = fmaxf(m0, tm0), nm1 = fmaxf(m1, tm1);
        const float c0 = ex2((m0 - nm0) * K2EXP);
        const float c1 = ex2((m1 - nm1) * K2EXP);
        m0 = nm0; m1 = nm1;
        l0 *= c0;  l1 *= c1;
        if (__any_sync(0xffffffffu, (c0 < 1.f) || (c1 < 1.f))) {
#pragma unroll
            for (int nt = 0; nt < 32; nt++) {
                o[nt][0] *= c0; o[nt][1] *= c0;
                o[nt][2] *= c1; o[nt][3] *= c1;
            }
        }
#pragma unroll
        for (int nt = 0; nt < 4; nt++) {
            S[nt][0] = ex2((S[nt][0] - m0) * K2EXP);
            S[nt][1] = ex2((S[nt][1] - m0) * K2EXP);
            S[nt][2] = ex2((S[nt][2] - m1) * K2EXP);
            S[nt][3] = ex2((S[nt][3] - m1) * K2EXP);
            l0 += S[nt][0] + S[nt][1];
            l1 += S[nt][2] + S[nt][3];
        }

        // ---- P fragments (hi/lo), direct C->A layout identity ----
        uint32_t pah[2][4], pal[2][4];
#pragma unroll
        for (int ks2 = 0; ks2 < 2; ks2++) {
            const int t0 = ks2 * 2, t1 = t0 + 1;
            float hv[8], lv[8];
            const float pv[8] = { S[t0][0], S[t0][1], S[t0][2], S[t0][3],
                                  S[t1][0], S[t1][1], S[t1][2], S[t1][3] };
#pragma unroll
            for (int e = 0; e < 8; e++) {
                __nv_bfloat16 hb = __float2bfloat16(pv[e]);
                hv[e] = __bfloat162float(hb);
                lv[e] = pv[e] - hv[e];
            }
            pah[ks2][0] = pack_bf16(hv[0], hv[1]);
            pah[ks2][1] = pack_bf16(hv[2], hv[3]);
            pah[ks2][2] = pack_bf16(hv[4], hv[5]);
            pah[ks2][3] = pack_bf16(hv[6], hv[7]);
            pal[ks2][0] = pack_bf16(lv[0], lv[1]);
            pal[ks2][1] = pack_bf16(lv[2], lv[3]);
            pal[ks2][2] = pack_bf16(lv[4], lv[5]);
            pal[ks2][3] = pack_bf16(lv[6], lv[7]);
        }

        // ---- O += P V (3-term) ----
#pragma unroll
        for (int ks2 = 0; ks2 < 2; ks2++) {
            const uint32_t vb = vAddr + (uint32_t)ks2 * 16 * QROWB;
#pragma unroll
            for (int g16 = 0; g16 < 16; g16++) {
                uint32_t vh[4], vl[4];
                ldsm4t(vh[0], vh[1], vh[2], vh[3], vb + g16 * 32);
                ldsm4t(vl[0], vl[1], vl[2], vl[3], vb + (FSM_VLO - FSM_VHI) + g16 * 32);
                const int n0 = g16 * 2, n1 = n0 + 1;
                mma16816(o[n0], pah[ks2], vh[0], vh[1]);
                mma16816(o[n0], pah[ks2], vl[0], vl[1]);
                mma16816(o[n0], pal[ks2], vh[0], vh[1]);
                mma16816(o[n1], pah[ks2], vh[2], vh[3]);
                mma16816(o[n1], pah[ks2], vl[2], vl[3]);
                mma16816(o[n1], pal[ks2], vh[2], vh[3]);
            }
        }
        __syncthreads();
    }

    // ---- epilogue: normalize, sigmoid gate, write bf16 hi/lo ----
    l0 += __shfl_xor_sync(0xffffffffu, l0, 1);
    l0 += __shfl_xor_sync(0xffffffffu, l0, 2);
    l1 += __shfl_xor_sync(0xffffffffu, l1, 1);
    l1 += __shfl_xor_sync(0xffffffffu, l1, 2);
    const float inv0 = frcp(l0), inv1 = frcp(l1);

#pragma unroll
    for (int nt = 0; nt < 32; nt++) {
#pragma unroll
        for (int e = 0; e < 4; e++) {
            const int row = qbase + g + (e >> 1) * 8;
            const int d   = nt * 8 + cb + (e & 1);
            const size_t idx = (size_t)(b * 2048 + row) * QDIM + h * HDIM + d;
            const float gt  = Gate[idx];
            const float sig = frcp(1.f + ex2(-gt * 1.4426950f));
            const float val = o[nt][e] * ((e < 2) ? inv0 : inv1) * sig;
            const __nv_bfloat16 hb = __float2bfloat16(val);
            Ohi[idx] = hb;
            Olo[idx] = __float2bfloat16(val - __bfloat162float(hb));
        }
    }
}

// ---------------- launcher ------------------------------------------------------
extern "C" void kernel_launch(void* const* d_in, const int* in_sizes, int n_in,
                              void* d_out, int out_size)
{
    const float* hidden = (const float*)d_in[0];
    const float* cosb   = (const float*)d_in[1];
    const float* sinb   = (const float*)d_in[2];
    const float* Wq     = (const float*)d_in[3];
    const float* Wk     = (const float*)d_in[4];
    const float* Wv     = (const float*)d_in[5];
    const float* Wo     = (const float*)d_in[6];
    const float* qnw    = (const float*)d_in[7];
    const float* knw    = (const float*)d_in[8];
    float* out = (float*)d_out;

    float *Qb, *Gb, *Kb, *Vb;
    cudaGetSymbolAddress((void**)&Qb, g_Q);
    cudaGetSymbolAddress((void**)&Gb, g_Gate);
    cudaGetSymbolAddress((void**)&Kb, g_K);
    cudaGetSymbolAddress((void**)&Vb, g_V);
    __nv_bfloat16 *hidH,*hidL,*WqH,*WqL,*WkH,*WkL,*WvH,*WvL,*WoH,*WoL,*AtH,*AtL;
    __nv_bfloat16 *QH,*QL,*KH,*KL,*VH,*VL;
    cudaGetSymbolAddress((void**)&hidH, g_hid_hi);  cudaGetSymbolAddress((void**)&hidL, g_hid_lo);
    cudaGetSymbolAddress((void**)&WqH,  g_Wq_hi);   cudaGetSymbolAddress((void**)&WqL,  g_Wq_lo);
    cudaGetSymbolAddress((void**)&WkH,  g_Wk_hi);   cudaGetSymbolAddress((void**)&WkL,  g_Wk_lo);
    cudaGetSymbolAddress((void**)&WvH,  g_Wv_hi);   cudaGetSymbolAddress((void**)&WvL,  g_Wv_lo);
    cudaGetSymbolAddress((void**)&WoH,  g_Wo_hi);   cudaGetSymbolAddress((void**)&WoL,  g_Wo_lo);
    cudaGetSymbolAddress((void**)&AtH,  g_Attn_hi); cudaGetSymbolAddress((void**)&AtL,  g_Attn_lo);
    cudaGetSymbolAddress((void**)&QH,   g_Qhi);     cudaGetSymbolAddress((void**)&QL,   g_Qlo);
    cudaGetSymbolAddress((void**)&KH,   g_Khi);     cudaGetSymbolAddress((void**)&KL,   g_Klo);
    cudaGetSymbolAddress((void**)&VH,   g_Vhi);     cudaGetSymbolAddress((void**)&VL,   g_Vlo);

    cudaFuncSetAttribute(gemm_hmma,  cudaFuncAttributeMaxDynamicSharedMemorySize, GSMEM);
    cudaFuncSetAttribute(flash_hmma, cudaFuncAttributeMaxDynamicSharedMemorySize, FSMEM);

    // 0) split fp32 -> bf16 hi/lo
    {
        int n;
        n = TOKENS * HIDDEN_ / 4;  split_bf16<<<(n+255)/256, 256>>>(hidden, hidH, hidL, n);
        n = QGDIM  * HIDDEN_ / 4;  split_bf16<<<(n+255)/256, 256>>>(Wq, WqH, WqL, n);
        n = KVDIM  * HIDDEN_ / 4;  split_bf16<<<(n+255)/256, 256>>>(Wk, WkH, WkL, n);
        n = KVDIM  * HIDDEN_ / 4;  split_bf16<<<(n+255)/256, 256>>>(Wv, WvH, WvL, n);
        n = HIDDEN_ * QDIM  / 4;   split_bf16<<<(n+255)/256, 256>>>(Wo, WoH, WoL, n);
    }

    // 1) QG projection (fused Q/gate de-interleave)
    gemm_hmma<<<dim3(QGDIM/128, TOKENS/128), 256, GSMEM>>>(
        hidH, hidL, WqH, WqL, Qb, Gb, HIDDEN_, QGDIM, 1);
    // 2,3) K and V projections
    gemm_hmma<<<dim3(KVDIM/128, TOKENS/128), 256, GSMEM>>>(
        hidH, hidL, WkH, WkL, Kb, nullptr, HIDDEN_, KVDIM, 0);
    gemm_hmma<<<dim3(KVDIM/128, TOKENS/128), 256, GSMEM>>>(
        hidH, hidL, WvH, WvL, Vb, nullptr, HIDDEN_, KVDIM, 0);
    // 4) RMSNorm + RoPE -> bf16 hi/lo
    rmsnorm_rope_split<<<dim3(TOKENS, NHEADS), 256>>>(Qb, qnw, cosb, sinb, QDIM,  QH, QL);
    rmsnorm_rope_split<<<dim3(TOKENS, NKV),    256>>>(Kb, knw, cosb, sinb, KVDIM, KH, KL);
    // 5) V -> bf16 hi/lo
    { int n = TOKENS * KVDIM / 4; split_bf16<<<(n+255)/256, 256>>>(Vb, VH, VL, n); }
    // 6) HMMA causal flash attention + sigmoid gate
    flash_hmma<<<dim3(2048/16, 4), 256, FSMEM>>>(QH, QL, KH, KL, VH, VL, Gb, AtH, AtL);
    // 7) output projection
    gemm_hmma<<<dim3(HIDDEN_/128, TOKENS/128), 256, GSMEM>>>(
        AtH, AtL, WoH, WoL, out, nullptr, QDIM, HIDDEN_, 0);
}

// round 11
// speedup vs baseline: 6.2372x; 1.2502x over previous
#include <cuda_runtime.h>
#include <cuda_bf16.h>
#include <cuda_fp16.h>
#include <math.h>
#include <stdint.h>

// Problem constants
#define TOKENS   4096          // B*S = 2*2048
#define HIDDEN_  2048
#define NHEADS   16
#define NKV      2
#define HDIM     256
#define QDIM     4096          // NHEADS*HDIM
#define KVDIM    512           // NKV*HDIM
#define ROT      64
#define SCALE    0.0625f       // 1/sqrt(256)
#define K2EXP    0.09016844f   // SCALE * log2(e)

// ---------------- scratch (allocation-free: __device__ globals) ----------------
__device__ float g_Q[(size_t)TOKENS * QDIM];      // raw Q output (pre-norm)
__device__ float g_Gate[(size_t)TOKENS * QDIM];
__device__ float g_K[(size_t)TOKENS * KVDIM];
__device__ float g_V[(size_t)TOKENS * KVDIM];

// bf16 hi/lo split operands
__device__ __nv_bfloat16 g_hid_hi[(size_t)TOKENS * HIDDEN_];
__device__ __nv_bfloat16 g_hid_lo[(size_t)TOKENS * HIDDEN_];
__device__ __half        g_hid_f16[(size_t)TOKENS * HIDDEN_];
__device__ __nv_bfloat16 g_WqQ_hi[(size_t)QDIM * HIDDEN_];    // gathered Q-half of Wq
__device__ __nv_bfloat16 g_WqQ_lo[(size_t)QDIM * HIDDEN_];
__device__ __half        g_Wqg_f16[(size_t)QDIM * HIDDEN_];   // gathered gate-half, fp16
__device__ __nv_bfloat16 g_Wk_hi[(size_t)KVDIM * HIDDEN_];
__device__ __nv_bfloat16 g_Wk_lo[(size_t)KVDIM * HIDDEN_];
__device__ __nv_bfloat16 g_Wv_hi[(size_t)KVDIM * HIDDEN_];
__device__ __nv_bfloat16 g_Wv_lo[(size_t)KVDIM * HIDDEN_];
__device__ __nv_bfloat16 g_Wo_hi[(size_t)HIDDEN_ * QDIM];
__device__ __nv_bfloat16 g_Wo_lo[(size_t)HIDDEN_ * QDIM];
__device__ __nv_bfloat16 g_Attn_hi[(size_t)TOKENS * QDIM];
__device__ __nv_bfloat16 g_Attn_lo[(size_t)TOKENS * QDIM];
// normalized+roped Q/K and V as bf16 hi/lo for HMMA flash
__device__ __nv_bfloat16 g_Qhi[(size_t)TOKENS * QDIM];
__device__ __nv_bfloat16 g_Qlo[(size_t)TOKENS * QDIM];
__device__ __nv_bfloat16 g_Khi[(size_t)TOKENS * KVDIM];
__device__ __nv_bfloat16 g_Klo[(size_t)TOKENS * KVDIM];
__device__ __nv_bfloat16 g_Vhi[(size_t)TOKENS * KVDIM];
__device__ __nv_bfloat16 g_Vlo[(size_t)TOKENS * KVDIM];

// =================== baseline-ISA helpers ===================
__device__ __forceinline__ uint32_t smem_u32(const void* p) {
    uint32_t a;
    asm("{ .reg .u64 t; cvta.to.shared.u64 t, %1; cvt.u32.u64 %0, t; }" : "=r"(a) : "l"(p));
    return a;
}
__device__ __forceinline__ void cp16(uint32_t s, const void* g) {
    asm volatile("cp.async.cg.shared.global [%0], [%1], 16;" :: "r"(s), "l"(g));
}
#define CP_COMMIT() asm volatile("cp.async.commit_group;" ::: "memory")
#define CP_WAIT(n)  asm volatile("cp.async.wait_group %0;" :: "n"(n) : "memory")

__device__ __forceinline__ void ldsm4(uint32_t& r0, uint32_t& r1, uint32_t& r2, uint32_t& r3,
                                      uint32_t addr) {
    asm volatile("ldmatrix.sync.aligned.m8n8.x4.shared.b16 {%0,%1,%2,%3}, [%4];"
        : "=r"(r0), "=r"(r1), "=r"(r2), "=r"(r3) : "r"(addr));
}
__device__ __forceinline__ void ldsm4t(uint32_t& r0, uint32_t& r1, uint32_t& r2, uint32_t& r3,
                                       uint32_t addr) {
    asm volatile("ldmatrix.sync.aligned.m8n8.x4.trans.shared.b16 {%0,%1,%2,%3}, [%4];"
        : "=r"(r0), "=r"(r1), "=r"(r2), "=r"(r3) : "r"(addr));
}
__device__ __forceinline__ void mma16816(float* d, const uint32_t* a, uint32_t b0, uint32_t b1) {
    asm volatile("mma.sync.aligned.m16n8k16.row.col.f32.bf16.bf16.f32 "
        "{%0,%1,%2,%3}, {%4,%5,%6,%7}, {%8,%9}, {%0,%1,%2,%3};"
        : "+f"(d[0]), "+f"(d[1]), "+f"(d[2]), "+f"(d[3])
        : "r"(a[0]), "r"(a[1]), "r"(a[2]), "r"(a[3]), "r"(b0), "r"(b1));
}
__device__ __forceinline__ void mma16816h(float* d, const uint32_t* a, uint32_t b0, uint32_t b1) {
    asm volatile("mma.sync.aligned.m16n8k16.row.col.f32.f16.f16.f32 "
        "{%0,%1,%2,%3}, {%4,%5,%6,%7}, {%8,%9}, {%0,%1,%2,%3};"
        : "+f"(d[0]), "+f"(d[1]), "+f"(d[2]), "+f"(d[3])
        : "r"(a[0]), "r"(a[1]), "r"(a[2]), "r"(a[3]), "r"(b0), "r"(b1));
}
__device__ __forceinline__ float ex2(float x) {
    float r; asm("ex2.approx.f32 %0, %1;" : "=f"(r) : "f"(x)); return r;
}
__device__ __forceinline__ float frcp(float x) {
    float r; asm("rcp.approx.f32 %0, %1;" : "=f"(r) : "f"(x)); return r;
}
__device__ __forceinline__ uint32_t pack_bf16(float lo, float hi) {
    uint32_t r;
    asm("cvt.rn.satfinite.bf16x2.f32 %0, %1, %2;" : "=r"(r) : "f"(hi), "f"(lo));
    return r;
}

// =================== conversion / gather kernels ===================
__device__ __forceinline__ void sp1(float x, __nv_bfloat16& h, __nv_bfloat16& l) {
    h = __float2bfloat16(x);
    l = __float2bfloat16(x - __bfloat162float(h));
}
__device__ __forceinline__ void wr_split(__nv_bfloat16* H, __nv_bfloat16* L, size_t i4, float4 x) {
    __nv_bfloat16 h0,h1,h2,h3,l0,l1,l2,l3;
    sp1(x.x,h0,l0); sp1(x.y,h1,l1); sp1(x.z,h2,l2); sp1(x.w,h3,l3);
    ((__nv_bfloat162*)H)[i4*2]   = __nv_bfloat162(h0,h1);
    ((__nv_bfloat162*)H)[i4*2+1] = __nv_bfloat162(h2,h3);
    ((__nv_bfloat162*)L)[i4*2]   = __nv_bfloat162(l0,l1);
    ((__nv_bfloat162*)L)[i4*2+1] = __nv_bfloat162(l2,l3);
}
__global__ void __launch_bounds__(256) split_bf16(
    const float* __restrict__ X, __nv_bfloat16* __restrict__ H,
    __nv_bfloat16* __restrict__ L, int n4)
{
    int i = blockIdx.x * 256 + threadIdx.x;
    if (i >= n4) return;
    wr_split(H, L, i, ((const float4*)X)[i]);
}
__global__ void __launch_bounds__(256) split_hid(
    const float* __restrict__ X, __nv_bfloat16* __restrict__ H,
    __nv_bfloat16* __restrict__ L, __half* __restrict__ F, int n4)
{
    int i = blockIdx.x * 256 + threadIdx.x;
    if (i >= n4) return;
    float4 x = ((const float4*)X)[i];
    wr_split(H, L, i, x);
    ((__half2*)F)[i*2]   = __half2(__float2half(x.x), __float2half(x.y));
    ((__half2*)F)[i*2+1] = __half2(__float2half(x.z), __float2half(x.w));
}
__global__ void __launch_bounds__(256) gather_wq_q(
    const float* __restrict__ Wq, __nv_bfloat16* __restrict__ H, __nv_bfloat16* __restrict__ L)
{
    int i = blockIdx.x * 256 + threadIdx.x;       // QDIM * 512
    if (i >= QDIM * (HIDDEN_/4)) return;
    const int n = i >> 9, c = i & 511;
    const int o = ((n >> 8) << 9) + (n & 255);
    wr_split(H, L, i, ((const float4*)Wq)[(size_t)o * 512 + c]);
}
__global__ void __launch_bounds__(256) gather_wq_g(
    const float* __restrict__ Wq, __half* __restrict__ F)
{
    int i = blockIdx.x * 256 + threadIdx.x;
    if (i >= QDIM * (HIDDEN_/4)) return;
    const int n = i >> 9, c = i & 511;
    const int o = ((n >> 8) << 9) + 256 + (n & 255);
    float4 x = ((const float4*)Wq)[(size_t)o * 512 + c];
    ((__half2*)F)[i*2]   = __half2(__float2half(x.x), __float2half(x.y));
    ((__half2*)F)[i*2+1] = __half2(__float2half(x.z), __float2half(x.w));
}

// =================== HMMA 3-term bf16-split GEMM ===================
#define GBK    32
#define ROWB   80
#define TILEB  (128 * ROWB)
#define STAGEB (4 * TILEB)
#define GSMEM  (2 * STAGEB)        // 81920

__device__ __forceinline__ void load_stage(
    uint32_t sbase, const __nv_bfloat16* __restrict__ Ahi, const __nv_bfloat16* __restrict__ Alo,
    const __nv_bfloat16* __restrict__ Bhi, const __nv_bfloat16* __restrict__ Blo,
    int rowBase, int colBase, int K, int k0, int tid)
{
#pragma unroll
    for (int i = 0; i < 8; i++) {
        const int t   = i >> 1;
        const int idx = ((i & 1) << 8) + tid;
        const int r   = idx >> 2;
        const int c   = idx & 3;
        const __nv_bfloat16* src = (t == 0) ? Ahi : (t == 1) ? Alo : (t == 2) ? Bhi : Blo;
        const int base = (t < 2) ? rowBase : colBase;
        cp16(sbase + t * TILEB + r * ROWB + c * 16,
             src + (size_t)(base + r) * K + k0 + c * 8);
    }
}

__global__ void __launch_bounds__(256, 2) gemm_hmma(
    const __nv_bfloat16* __restrict__ Ahi, const __nv_bfloat16* __restrict__ Alo,
    const __nv_bfloat16* __restrict__ Bhi, const __nv_bfloat16* __restrict__ Blo,
    float* __restrict__ C0, int K, int N)
{
    extern __shared__ char smem[];
    const uint32_t sbase = smem_u32(smem);
    const int tid  = threadIdx.x;
    const int w    = tid >> 5;
    const int lane = tid & 31;
    const int rowBase = blockIdx.y * 128;
    const int colBase = blockIdx.x * 128;
    const int wm = (w & 1) * 64;
    const int wn = (w >> 1) * 32;

    float acc[4][4][4];
#pragma unroll
    for (int mi = 0; mi < 4; mi++)
#pragma unroll
        for (int nj = 0; nj < 4; nj++)
#pragma unroll
            for (int e = 0; e < 4; e++) acc[mi][nj][e] = 0.f;

    const uint32_t aRowOff = (uint32_t)(wm + (lane & 15)) * ROWB + ((lane >> 4) & 1) * 16;
    const uint32_t bRowOff = (uint32_t)(wn + (lane & 7) + ((lane >> 4) & 1) * 8) * ROWB
                           + ((lane >> 3) & 1) * 16;

    const int KT = K / GBK;
    load_stage(sbase, Ahi, Alo, Bhi, Blo, rowBase, colBase, K, 0, tid);
    CP_COMMIT();

    for (int kt = 0; kt < KT; kt++) {
        if (kt + 1 < KT) {
            load_stage(sbase + ((kt + 1) & 1) * STAGEB, Ahi, Alo, Bhi, Blo,
                       rowBase, colBase, K, (kt + 1) * GBK, tid);
            CP_COMMIT();
            CP_WAIT(1);
        } else {
            CP_WAIT(0);
        }
        __syncthreads();

        const uint32_t st = sbase + (kt & 1) * STAGEB;
#pragma unroll
        for (int s = 0; s < 2; s++) {
            const uint32_t kb = s * 32;
            uint32_t bh[2][4], bl[2][4];
#pragma unroll
            for (int pi = 0; pi < 2; pi++) {
                const uint32_t off = bRowOff + (uint32_t)pi * 16 * ROWB + kb;
                ldsm4(bh[pi][0], bh[pi][1], bh[pi][2], bh[pi][3], st + 2 * TILEB + off);
                ldsm4(bl[pi][0], bl[pi][1], bl[pi][2], bl[pi][3], st + 3 * TILEB + off);
            }
#pragma unroll
            for (int mi = 0; mi < 4; mi++) {
                const uint32_t off = aRowOff + (uint32_t)mi * 16 * ROWB + kb;
                uint32_t ah[4], al[4];
                ldsm4(ah[0], ah[1], ah[2], ah[3], st + 0 * TILEB + off);
                ldsm4(al[0], al[1], al[2], al[3], st + 1 * TILEB + off);
#pragma unroll
                for (int pi = 0; pi < 2; pi++)
#pragma unroll
                    for (int hf = 0; hf < 2; hf++) {
                        const int nj = pi * 2 + hf;
                        mma16816(acc[mi][nj], ah, bh[pi][hf*2], bh[pi][hf*2+1]);
                        mma16816(acc[mi][nj], ah, bl[pi][hf*2], bl[pi][hf*2+1]);
                        mma16816(acc[mi][nj], al, bh[pi][hf*2], bh[pi][hf*2+1]);
                    }
            }
        }
        __syncthreads();
    }

    const int lr = lane >> 2;
    const int lc = (lane & 3) * 2;
#pragma unroll
    for (int mi = 0; mi < 4; mi++)
#pragma unroll
        for (int nj = 0; nj < 4; nj++) {
            const int r0 = rowBase + wm + mi * 16 + lr;
            const int cg = colBase + wn + nj * 8 + lc;
            *(float2*)(C0 + (size_t)r0 * N + cg)       = make_float2(acc[mi][nj][0], acc[mi][nj][1]);
            *(float2*)(C0 + (size_t)(r0 + 8) * N + cg) = make_float2(acc[mi][nj][2], acc[mi][nj][3]);
        }
}

// =================== fp16 single-term GEMM (gate path) ===================
#define HTILEB  (128 * ROWB)
#define HSTAGEB (2 * HTILEB)
#define HSMEM   (2 * HSTAGEB)      // 40960

__global__ void __launch_bounds__(256, 2) gemm_f16(
    const __half* __restrict__ A, const __half* __restrict__ B,
    float* __restrict__ C, int K, int N)
{
    extern __shared__ char smem[];
    const uint32_t sbase = smem_u32(smem);
    const int tid  = threadIdx.x;
    const int w    = tid >> 5;
    const int lane = tid & 31;
    const int rowBase = blockIdx.y * 128;
    const int colBase = blockIdx.x * 128;
    const int wm = (w & 1) * 64;
    const int wn = (w >> 1) * 32;

    float acc[4][4][4];
#pragma unroll
    for (int mi = 0; mi < 4; mi++)
#pragma unroll
        for (int nj = 0; nj < 4; nj++)
#pragma unroll
            for (int e = 0; e < 4; e++) acc[mi][nj][e] = 0.f;

    const uint32_t aRowOff = (uint32_t)(wm + (lane & 15)) * ROWB + ((lane >> 4) & 1) * 16;
    const uint32_t bRowOff = (uint32_t)(wn + (lane & 7) + ((lane >> 4) & 1) * 8) * ROWB
                           + ((lane >> 3) & 1) * 16;

    const int KT = K / GBK;
#pragma unroll
    for (int i = 0; i < 4; i++) {
        const int t = i >> 1;
        const int idx = ((i & 1) << 8) + tid;
        const int r = idx >> 2, c = idx & 3;
        const __half* src = t ? B : A;
        const int base = t ? colBase : rowBase;
        cp16(sbase + t * HTILEB + r * ROWB + c * 16,
             src + (size_t)(base + r) * K + c * 8);
    }
    CP_COMMIT();

    for (int kt = 0; kt < KT; kt++) {
        if (kt + 1 < KT) {
            const int k0 = (kt + 1) * GBK;
            const uint32_t sb2 = sbase + ((kt + 1) & 1) * HSTAGEB;
#pragma unroll
            for (int i = 0; i < 4; i++) {
                const int t = i >> 1;
                const int idx = ((i & 1) << 8) + tid;
                const int r = idx >> 2, c = idx & 3;
                const __half* src = t ? B : A;
                const int base = t ? colBase : rowBase;
                cp16(sb2 + t * HTILEB + r * ROWB + c * 16,
                     src + (size_t)(base + r) * K + k0 + c * 8);
            }
            CP_COMMIT();
            CP_WAIT(1);
        } else {
            CP_WAIT(0);
        }
        __syncthreads();

        const uint32_t st = sbase + (kt & 1) * HSTAGEB;
#pragma unroll
        for (int s = 0; s < 2; s++) {
            const uint32_t kb = s * 32;
            uint32_t bf[2][4];
#pragma unroll
            for (int pi = 0; pi < 2; pi++) {
                const uint32_t off = bRowOff + (uint32_t)pi * 16 * ROWB + kb;
                ldsm4(bf[pi][0], bf[pi][1], bf[pi][2], bf[pi][3], st + HTILEB + off);
            }
#pragma unroll
            for (int mi = 0; mi < 4; mi++) {
                const uint32_t off = aRowOff + (uint32_t)mi * 16 * ROWB + kb;
                uint32_t af[4];
                ldsm4(af[0], af[1], af[2], af[3], st + off);
#pragma unroll
                for (int pi = 0; pi < 2; pi++)
#pragma unroll
                    for (int hf = 0; hf < 2; hf++)
                        mma16816h(acc[mi][pi*2+hf], af, bf[pi][hf*2], bf[pi][hf*2+1]);
            }
        }
        __syncthreads();
    }

    const int lr = lane >> 2;
    const int lc = (lane & 3) * 2;
#pragma unroll
    for (int mi = 0; mi < 4; mi++)
#pragma unroll
        for (int nj = 0; nj < 4; nj++) {
            const int r0 = rowBase + wm + mi * 16 + lr;
            const int cg = colBase + wn + nj * 8 + lc;
            *(float2*)(C + (size_t)r0 * N + cg)       = make_float2(acc[mi][nj][0], acc[mi][nj][1]);
            *(float2*)(C + (size_t)(r0 + 8) * N + cg) = make_float2(acc[mi][nj][2], acc[mi][nj][3]);
        }
}

// ---------------- fused RMSNorm + partial RoPE -> bf16 hi/lo --------------------
__global__ void __launch_bounds__(256) rmsnorm_rope_split(
    const float* __restrict__ X, const float* __restrict__ w,
    const float* __restrict__ cosb, const float* __restrict__ sinb, int stride,
    __nv_bfloat16* __restrict__ H, __nv_bfloat16* __restrict__ L)
{
    const int t = blockIdx.x;
    const int h = blockIdx.y;
    const int d = threadIdx.x;
    const float* xp = X + (size_t)t * stride + h * HDIM;
    float x = xp[d];

    float ss = x * x;
#pragma unroll
    for (int off = 16; off; off >>= 1) ss += __shfl_xor_sync(0xffffffffu, ss, off);
    __shared__ float red[8];
    if ((d & 31) == 0) red[d >> 5] = ss;
    __syncthreads();
    float sum = red[0] + red[1] + red[2] + red[3] + red[4] + red[5] + red[6] + red[7];
    float inv = rsqrtf(sum * (1.f / 256.f) + 1e-6f);
    float n = x * inv * w[d];

    __shared__ float sn[ROT];
    if (d < ROT) sn[d] = n;
    __syncthreads();

    float out = n;
    if (d < 32) {
        float c = cosb[t * ROT + d], s = sinb[t * ROT + d];
        out = n * c - sn[d + 32] * s;
    } else if (d < ROT) {
        float c = cosb[t * ROT + d], s = sinb[t * ROT + d];
        out = n * c + sn[d - 32] * s;
    }
    const size_t idx = (size_t)t * stride + h * HDIM + d;
    __nv_bfloat16 hi = __float2bfloat16(out);
    H[idx] = hi;
    L[idx] = __float2bfloat16(out - __bfloat162float(hi));
}

// =================== HMMA flash attention (unchanged from R10) ==================
#define QROWB  528
#define FSM_QHI 0
#define FSM_QLO (128 * QROWB)
#define FSM_KHI (256 * QROWB)
#define FSM_KLO (288 * QROWB)
#define FSM_VHI (320 * QROWB)
#define FSM_VLO (352 * QROWB)
#define FSMEM   (384 * QROWB)

__global__ void __launch_bounds__(256, 1) flash_hmma(
    const __nv_bfloat16* __restrict__ Qhi, const __nv_bfloat16* __restrict__ Qlo,
    const __nv_bfloat16* __restrict__ Khi, const __nv_bfloat16* __restrict__ Klo,
    const __nv_bfloat16* __restrict__ Vhi, const __nv_bfloat16* __restrict__ Vlo,
    const float* __restrict__ Gate,
    __nv_bfloat16* __restrict__ Ohi, __nv_bfloat16* __restrict__ Olo)
{
    extern __shared__ char smem[];
    const uint32_t sb = smem_u32(smem);
    const int tid  = threadIdx.x;
    const int warp = tid >> 5;
    const int lane = tid & 31;
    const int qblk = blockIdx.x;
    const int b    = blockIdx.y >> 1;
    const int kvh  = blockIdx.y & 1;
    const int qbase = qblk * 16;
    const int h    = kvh * 8 + warp;

    for (int i = tid; i < 4096; i += 256) {
        const int r = i >> 5;
        const int c = i & 31;
        const size_t src = (size_t)(b * 2048 + qbase + (r & 15)) * QDIM
                         + (kvh * 8 + (r >> 4)) * HDIM + c * 8;
        const uint32_t dst = (uint32_t)r * QROWB + c * 16;
        cp16(sb + FSM_QHI + dst, Qhi + src);
        cp16(sb + FSM_QLO + dst, Qlo + src);
    }
    CP_COMMIT();

    float o[32][4];
#pragma unroll
    for (int nt = 0; nt < 32; nt++)
#pragma unroll
        for (int e = 0; e < 4; e++) o[nt][e] = 0.f;
    float m0 = -1e30f, m1 = -1e30f, l0 = 0.f, l1 = 0.f;

    const int g  = lane >> 2;
    const int cb = (lane & 3) * 2;

    const uint32_t qAddrHi = sb + FSM_QHI + (uint32_t)(warp * 16 + (lane & 15)) * QROWB
                           + ((lane >> 4) & 1) * 16;
    const uint32_t qAddrLo = qAddrHi + (FSM_QLO - FSM_QHI);
    const uint32_t kAddr   = sb + FSM_KHI
                           + (uint32_t)((lane & 7) + ((lane >> 4) & 1) * 8) * QROWB
                           + ((lane >> 3) & 1) * 16;
    const uint32_t vAddr   = sb + FSM_VHI + (uint32_t)(lane & 15) * QROWB + (lane >> 4) * 16;

    const int ntiles = ((qbase + 15) >> 5) + 1;
    CP_WAIT(0);
    __syncthreads();

    for (int it = 0; it < ntiles; it++) {
        const int j0 = it * 32;
        for (int i = tid; i < 1024; i += 256) {
            const int r = i >> 5, c = i & 31;
            const int kr = min(j0 + r, 2047);
            const size_t src = (size_t)(b * 2048 + kr) * KVDIM + kvh * HDIM + c * 8;
            const uint32_t dst = (uint32_t)r * QROWB + c * 16;
            cp16(sb + FSM_KHI + dst, Khi + src);
            cp16(sb + FSM_KLO + dst, Klo + src);
            cp16(sb + FSM_VHI + dst, Vhi + src);
            cp16(sb + FSM_VLO + dst, Vlo + src);
        }
        CP_COMMIT(); CP_WAIT(0);
        __syncthreads();

        float S[4][4];
#pragma unroll
        for (int nt = 0; nt < 4; nt++)
#pragma unroll
            for (int e = 0; e < 4; e++) S[nt][e] = 0.f;

#pragma unroll
        for (int ks = 0; ks < 16; ks++) {
            uint32_t qh[4], ql[4], k0h[4], k1h[4], k0l[4], k1l[4];
            ldsm4(qh[0], qh[1], qh[2], qh[3], qAddrHi + ks * 32);
            ldsm4(ql[0], ql[1], ql[2], ql[3], qAddrLo + ks * 32);
            ldsm4(k0h[0], k0h[1], k0h[2], k0h[3], kAddr + ks * 32);
            ldsm4(k1h[0], k1h[1], k1h[2], k1h[3], kAddr + 16 * QROWB + ks * 32);
            ldsm4(k0l[0], k0l[1], k0l[2], k0l[3], kAddr + (FSM_KLO - FSM_KHI) + ks * 32);
            ldsm4(k1l[0], k1l[1], k1l[2], k1l[3], kAddr + (FSM_KLO - FSM_KHI) + 16 * QROWB + ks * 32);
            mma16816(S[0], qh, k0h[0], k0h[1]);
            mma16816(S[0], qh, k0l[0], k0l[1]);
            mma16816(S[0], ql, k0h[0], k0h[1]);
            mma16816(S[1], qh, k0h[2], k0h[3]);
            mma16816(S[1], qh, k0l[2], k0l[3]);
            mma16816(S[1], ql, k0h[2], k0h[3]);
            mma16816(S[2], qh, k1h[0], k1h[1]);
            mma16816(S[2], qh, k1l[0], k1l[1]);
            mma16816(S[2], ql, k1h[0], k1h[1]);
            mma16816(S[3], qh, k1h[2], k1h[3]);
            mma16816(S[3], qh, k1l[2], k1l[3]);
            mma16816(S[3], ql, k1h[2], k1h[3]);
        }

        if (it == ntiles - 1) {
#pragma unroll
            for (int nt = 0; nt < 4; nt++)
#pragma unroll
                for (int e = 0; e < 4; e++) {
                    const int row = qbase + g + (e >> 1) * 8;
                    const int col = j0 + nt * 8 + cb + (e & 1);
                    if (col > row) S[nt][e] = -1e30f;
                }
        }

        float tm0 = -1e30f, tm1 = -1e30f;
#pragma unroll
        for (int nt = 0; nt < 4; nt++) {
            tm0 = fmaxf(tm0, fmaxf(S[nt][0], S[nt][1]));
            tm1 = fmaxf(tm1, fmaxf(S[nt][2], S[nt][3]));
        }
        tm0 = fmaxf(tm0, __shfl_xor_sync(0xffffffffu, tm0, 1));
        tm0 = fmaxf(tm0, __shfl_xor_sync(0xffffffffu, tm0, 2));
        tm1 = fmaxf(tm1, __shfl_xor_sync(0xffffffffu, tm1, 1));
        tm1 = fmaxf(tm1, __shfl_xor_sync(0xffffffffu, tm1, 2));
        const float nm0 = fmaxf(m0, tm0), nm1 = fmaxf(m1, tm1);
        const float c0 = ex2((m0 - nm0) * K2EXP);
        const float c1 = ex2((m1 - nm1) * K2EXP);
        m0 = nm0; m1 = nm1;
        l0 *= c0;  l1 *= c1;
        if (__any_sync(0xffffffffu, (c0 < 1.f) || (c1 < 1.f))) {
#pragma unroll
            for (int nt = 0; nt < 32; nt++) {
                o[nt][0] *= c0; o[nt][1] *= c0;
                o[nt][2] *= c1; o[nt][3] *= c1;
            }
        }
#pragma unroll
        for (int nt = 0; nt < 4; nt++) {
            S[nt][0] = ex2((S[nt][0] - m0) * K2EXP);
            S[nt][1] = ex2((S[nt][1] - m0) * K2EXP);
            S[nt][2] = ex2((S[nt][2] - m1) * K2EXP);
            S[nt][3] = ex2((S[nt][3] - m1) * K2EXP);
            l0 += S[nt][0] + S[nt][1];
            l1 += S[nt][2] + S[nt][3];
        }

        uint32_t pah[2][4], pal[2][4];
#pragma unroll
        for (int ks2 = 0; ks2 < 2; ks2++) {
            const int t0 = ks2 * 2, t1 = t0 + 1;
            float hv[8], lv[8];
            const float pv[8] = { S[t0][0], S[t0][1], S[t0][2], S[t0][3],
                                  S[t1][0], S[t1][1], S[t1][2], S[t1][3] };
#pragma unroll
            for (int e = 0; e < 8; e++) {
                __nv_bfloat16 hb = __float2bfloat16(pv[e]);
                hv[e] = __bfloat162float(hb);
                lv[e] = pv[e] - hv[e];
            }
            pah[ks2][0] = pack_bf16(hv[0], hv[1]);
            pah[ks2][1] = pack_bf16(hv[2], hv[3]);
            pah[ks2][2] = pack_bf16(hv[4], hv[5]);
            pah[ks2][3] = pack_bf16(hv[6], hv[7]);
            pal[ks2][0] = pack_bf16(lv[0], lv[1]);
            pal[ks2][1] = pack_bf16(lv[2], lv[3]);
            pal[ks2][2] = pack_bf16(lv[4], lv[5]);
            pal[ks2][3] = pack_bf16(lv[6], lv[7]);
        }

#pragma unroll
        for (int ks2 = 0; ks2 < 2; ks2++) {
            const uint32_t vb = vAddr + (uint32_t)ks2 * 16 * QROWB;
#pragma unroll
            for (int g16 = 0; g16 < 16; g16++) {
                uint32_t vh[4], vl[4];
                ldsm4t(vh[0], vh[1], vh[2], vh[3], vb + g16 * 32);
                ldsm4t(vl[0], vl[1], vl[2], vl[3], vb + (FSM_VLO - FSM_VHI) + g16 * 32);
                const int n0 = g16 * 2, n1 = n0 + 1;
                mma16816(o[n0], pah[ks2], vh[0], vh[1]);
                mma16816(o[n0], pah[ks2], vl[0], vl[1]);
                mma16816(o[n0], pal[ks2], vh[0], vh[1]);
                mma16816(o[n1], pah[ks2], vh[2], vh[3]);
                mma16816(o[n1], pah[ks2], vl[2], vl[3]);
                mma16816(o[n1], pal[ks2], vh[2], vh[3]);
            }
        }
        __syncthreads();
    }

    l0 += __shfl_xor_sync(0xffffffffu, l0, 1);
    l0 += __shfl_xor_sync(0xffffffffu, l0, 2);
    l1 += __shfl_xor_sync(0xffffffffu, l1, 1);
    l1 += __shfl_xor_sync(0xffffffffu, l1, 2);
    const float inv0 = frcp(l0), inv1 = frcp(l1);

#pragma unroll
    for (int nt = 0; nt < 32; nt++) {
#pragma unroll
        for (int e = 0; e < 4; e++) {
            const int row = qbase + g + (e >> 1) * 8;
            const int d   = nt * 8 + cb + (e & 1);
            const size_t idx = (size_t)(b * 2048 + row) * QDIM + h * HDIM + d;
            const float gt  = Gate[idx];
            const float sig = frcp(1.f + ex2(-gt * 1.4426950f));
            const float val = o[nt][e] * ((e < 2) ? inv0 : inv1) * sig;
            const __nv_bfloat16 hb = __float2bfloat16(val);
            Ohi[idx] = hb;
            Olo[idx] = __float2bfloat16(val - __bfloat162float(hb));
        }
    }
}

// ---------------- launcher ------------------------------------------------------
extern "C" void kernel_launch(void* const* d_in, const int* in_sizes, int n_in,
                              void* d_out, int out_size)
{
    const float* hidden = (const float*)d_in[0];
    const float* cosb   = (const float*)d_in[1];
    const float* sinb   = (const float*)d_in[2];
    const float* Wq     = (const float*)d_in[3];
    const float* Wk     = (const float*)d_in[4];
    const float* Wv     = (const float*)d_in[5];
    const float* Wo     = (const float*)d_in[6];
    const float* qnw    = (const float*)d_in[7];
    const float* knw    = (const float*)d_in[8];
    float* out = (float*)d_out;

    float *Qb, *Gb, *Kb, *Vb;
    cudaGetSymbolAddress((void**)&Qb, g_Q);
    cudaGetSymbolAddress((void**)&Gb, g_Gate);
    cudaGetSymbolAddress((void**)&Kb, g_K);
    cudaGetSymbolAddress((void**)&Vb, g_V);
    __nv_bfloat16 *hidH,*hidL,*WqQH,*WqQL,*WkH,*WkL,*WvH,*WvL,*WoH,*WoL,*AtH,*AtL;
    __nv_bfloat16 *QH,*QL,*KH,*KL,*VH,*VL;
    __half *hidF, *WqgF;
    cudaGetSymbolAddress((void**)&hidH, g_hid_hi);  cudaGetSymbolAddress((void**)&hidL, g_hid_lo);
    cudaGetSymbolAddress((void**)&hidF, g_hid_f16);
    cudaGetSymbolAddress((void**)&WqQH, g_WqQ_hi);  cudaGetSymbolAddress((void**)&WqQL, g_WqQ_lo);
    cudaGetSymbolAddress((void**)&WqgF, g_Wqg_f16);
    cudaGetSymbolAddress((void**)&WkH,  g_Wk_hi);   cudaGetSymbolAddress((void**)&WkL,  g_Wk_lo);
    cudaGetSymbolAddress((void**)&WvH,  g_Wv_hi);   cudaGetSymbolAddress((void**)&WvL,  g_Wv_lo);
    cudaGetSymbolAddress((void**)&WoH,  g_Wo_hi);   cudaGetSymbolAddress((void**)&WoL,  g_Wo_lo);
    cudaGetSymbolAddress((void**)&AtH,  g_Attn_hi); cudaGetSymbolAddress((void**)&AtL,  g_Attn_lo);
    cudaGetSymbolAddress((void**)&QH,   g_Qhi);     cudaGetSymbolAddress((void**)&QL,   g_Qlo);
    cudaGetSymbolAddress((void**)&KH,   g_Khi);     cudaGetSymbolAddress((void**)&KL,   g_Klo);
    cudaGetSymbolAddress((void**)&VH,   g_Vhi);     cudaGetSymbolAddress((void**)&VL,   g_Vlo);

    cudaFuncSetAttribute(gemm_hmma,  cudaFuncAttributeMaxDynamicSharedMemorySize, GSMEM);
    cudaFuncSetAttribute(gemm_f16,   cudaFuncAttributeMaxDynamicSharedMemorySize, HSMEM);
    cudaFuncSetAttribute(flash_hmma, cudaFuncAttributeMaxDynamicSharedMemorySize, FSMEM);

    // 0) conversions / gathers
    {
        int n;
        n = TOKENS * HIDDEN_ / 4;  split_hid<<<(n+255)/256, 256>>>(hidden, hidH, hidL, hidF, n);
        n = QDIM * HIDDEN_ / 4;
        gather_wq_q<<<(n+255)/256, 256>>>(Wq, WqQH, WqQL);
        gather_wq_g<<<(n+255)/256, 256>>>(Wq, WqgF);
        n = KVDIM  * HIDDEN_ / 4;  split_bf16<<<(n+255)/256, 256>>>(Wk, WkH, WkL, n);
        n = KVDIM  * HIDDEN_ / 4;  split_bf16<<<(n+255)/256, 256>>>(Wv, WvH, WvL, n);
        n = HIDDEN_ * QDIM  / 4;   split_bf16<<<(n+255)/256, 256>>>(Wo, WoH, WoL, n);
    }

    // 1) Q projection (3-term bf16, head-major) + gate projection (1-term fp16)
    gemm_hmma<<<dim3(QDIM/128, TOKENS/128), 256, GSMEM>>>(
        hidH, hidL, WqQH, WqQL, Qb, HIDDEN_, QDIM);
    gemm_f16<<<dim3(QDIM/128, TOKENS/128), 256, HSMEM>>>(
        hidF, WqgF, Gb, HIDDEN_, QDIM);
    // 2,3) K and V projections
    gemm_hmma<<<dim3(KVDIM/128, TOKENS/128), 256, GSMEM>>>(
        hidH, hidL, WkH, WkL, Kb, HIDDEN_, KVDIM);
    gemm_hmma<<<dim3(KVDIM/128, TOKENS/128), 256, GSMEM>>>(
        hidH, hidL, WvH, WvL, Vb, HIDDEN_, KVDIM);
    // 4) RMSNorm + RoPE -> bf16 hi/lo
    rmsnorm_rope_split<<<dim3(TOKENS, NHEADS), 256>>>(Qb, qnw, cosb, sinb, QDIM,  QH, QL);
    rmsnorm_rope_split<<<dim3(TOKENS, NKV),    256>>>(Kb, knw, cosb, sinb, KVDIM, KH, KL);
    // 5) V -> bf16 hi/lo
    { int n = TOKENS * KVDIM / 4; split_bf16<<<(n+255)/256, 256>>>(Vb, VH, VL, n); }
    // 6) HMMA causal flash attention + sigmoid gate
    flash_hmma<<<dim3(2048/16, 4), 256, FSMEM>>>(QH, QL, KH, KL, VH, VL, Gb, AtH, AtL);
    // 7) output projection: C[4096,2048] = Attn[4096,4096] x Wo[2048,4096]^T
    gemm_hmma<<<dim3(HIDDEN_/128, TOKENS/128), 256, GSMEM>>>(
        AtH, AtL, WoH, WoL, out, QDIM, HIDDEN_);
}

// round 12
// speedup vs baseline: 7.7355x; 1.2402x over previous
#include <cuda_runtime.h>
#include <cuda_fp16.h>
#include <math.h>
#include <stdint.h>

// Problem constants
#define TOKENS   4096          // B*S
#define HIDDEN_  2048
#define NHEADS   16
#define NKV      2
#define HDIM     256
#define QDIM     4096
#define KVDIM    512
#define ROT      64
#define K2EXP    0.09016844f   // (1/sqrt(256)) * log2(e)

// fused projection layout: cols [0,4096) Q | [4096,4608) K | [4608,5120) V | [5120,9216) gate
#define PROJ_N   9216
#define SPLITC   4608          // fp32-out columns below, fp16-out above
#define GATE_C   5120          // gate columns (1-term) start here

// ---------------- scratch ----------------
__device__ __half g_hidH[(size_t)TOKENS * HIDDEN_];
__device__ __half g_hidL[(size_t)TOKENS * HIDDEN_];
__device__ __half g_Wcat[(size_t)PROJ_N * HIDDEN_];     // concat Q|K|V|gate weights, fp16
__device__ __half g_WoH[(size_t)HIDDEN_ * QDIM];
__device__ __half g_WoL[(size_t)HIDDEN_ * QDIM];
__device__ float  g_P32[(size_t)TOKENS * SPLITC];       // Q,K raw (pre-norm) fp32
__device__ __half g_P16[(size_t)TOKENS * SPLITC];       // cols' 0..511 = V, 512..4607 = gate
__device__ __half g_Qf [(size_t)TOKENS * QDIM];         // normalized+roped Q, fp16
__device__ __half g_KH [(size_t)TOKENS * KVDIM];        // normalized+roped K hi
__device__ __half g_KL [(size_t)TOKENS * KVDIM];        // K lo
__device__ __half g_Attn[(size_t)TOKENS * QDIM];        // gated attention out, fp16

// =================== helpers ===================
__device__ __forceinline__ uint32_t smem_u32(const void* p) {
    uint32_t a;
    asm("{ .reg .u64 t; cvta.to.shared.u64 t, %1; cvt.u32.u64 %0, t; }" : "=r"(a) : "l"(p));
    return a;
}
__device__ __forceinline__ void cp16(uint32_t s, const void* g) {
    asm volatile("cp.async.cg.shared.global [%0], [%1], 16;" :: "r"(s), "l"(g));
}
#define CP_COMMIT() asm volatile("cp.async.commit_group;" ::: "memory")
#define CP_WAIT(n)  asm volatile("cp.async.wait_group %0;" :: "n"(n) : "memory")

__device__ __forceinline__ void ldsm4(uint32_t& r0, uint32_t& r1, uint32_t& r2, uint32_t& r3,
                                      uint32_t addr) {
    asm volatile("ldmatrix.sync.aligned.m8n8.x4.shared.b16 {%0,%1,%2,%3}, [%4];"
        : "=r"(r0), "=r"(r1), "=r"(r2), "=r"(r3) : "r"(addr));
}
__device__ __forceinline__ void ldsm4t(uint32_t& r0, uint32_t& r1, uint32_t& r2, uint32_t& r3,
                                       uint32_t addr) {
    asm volatile("ldmatrix.sync.aligned.m8n8.x4.trans.shared.b16 {%0,%1,%2,%3}, [%4];"
        : "=r"(r0), "=r"(r1), "=r"(r2), "=r"(r3) : "r"(addr));
}
__device__ __forceinline__ void mmah(float* d, const uint32_t* a, uint32_t b0, uint32_t b1) {
    asm volatile("mma.sync.aligned.m16n8k16.row.col.f32.f16.f16.f32 "
        "{%0,%1,%2,%3}, {%4,%5,%6,%7}, {%8,%9}, {%0,%1,%2,%3};"
        : "+f"(d[0]), "+f"(d[1]), "+f"(d[2]), "+f"(d[3])
        : "r"(a[0]), "r"(a[1]), "r"(a[2]), "r"(a[3]), "r"(b0), "r"(b1));
}
__device__ __forceinline__ float ex2(float x) {
    float r; asm("ex2.approx.f32 %0, %1;" : "=f"(r) : "f"(x)); return r;
}
__device__ __forceinline__ float frcp(float x) {
    float r; asm("rcp.approx.f32 %0, %1;" : "=f"(r) : "f"(x)); return r;
}
__device__ __forceinline__ uint32_t pack_f16(float lo, float hi) {
    uint32_t r;
    asm("cvt.rn.f16x2.f32 %0, %1, %2;" : "=r"(r) : "f"(hi), "f"(lo));
    return r;
}

// =================== conversion kernels ===================
__global__ void __launch_bounds__(256) split_f16(
    const float* __restrict__ X, __half* __restrict__ H, __half* __restrict__ L, int n4)
{
    int i = blockIdx.x * 256 + threadIdx.x;
    if (i >= n4) return;
    float4 x = ((const float4*)X)[i];
    __half h0 = __float2half(x.x), h1 = __float2half(x.y);
    __half h2 = __float2half(x.z), h3 = __float2half(x.w);
    ((__half2*)H)[i*2]   = __half2(h0, h1);
    ((__half2*)H)[i*2+1] = __half2(h2, h3);
    ((__half2*)L)[i*2]   = __half2(__float2half(x.x - __half2float(h0)),
                                   __float2half(x.y - __half2float(h1)));
    ((__half2*)L)[i*2+1] = __half2(__float2half(x.z - __half2float(h2)),
                                   __float2half(x.w - __half2float(h3)));
}

// build concatenated weight matrix [9216][2048] fp16 (Q head-major | K | V | gate head-major)
__global__ void __launch_bounds__(256) conv_wcat(
    const float* __restrict__ Wq, const float* __restrict__ Wk,
    const float* __restrict__ Wv, __half* __restrict__ Wcat)
{
    int i = blockIdx.x * 256 + threadIdx.x;
    if (i >= PROJ_N * (HIDDEN_/4)) return;
    const int n = i >> 9, c = i & 511;
    const float* base;
    if (n < 4096)       base = Wq + (size_t)(((n >> 8) << 9) + (n & 255)) * HIDDEN_;
    else if (n < 4608)  base = Wk + (size_t)(n - 4096) * HIDDEN_;
    else if (n < 5120)  base = Wv + (size_t)(n - 4608) * HIDDEN_;
    else { int m = n - 5120; base = Wq + (size_t)(((m >> 8) << 9) + 256 + (m & 255)) * HIDDEN_; }
    float4 x = ((const float4*)base)[c];
    __half2* dst = (__half2*)(Wcat + (size_t)n * HIDDEN_);
    dst[c*2]   = __half2(__float2half(x.x), __float2half(x.y));
    dst[c*2+1] = __half2(__float2half(x.z), __float2half(x.w));
}

// =================== fused projection GEMM ===================
// P[4096, 9216] = hid[4096,2048] x Wcat[9216,2048]^T
// A split (fp16 hi/lo, 2-term) except gate cols (1-term). out fp32 (cols<4608) / fp16.
#define GBK     32
#define ROWB    80
#define TILEB   (128 * ROWB)       // 10240
#define STAGE3B (3 * TILEB)        // Ah, Al, B
#define PSMEM   (3 * STAGE3B)      // 92160, 3 stages

__device__ __forceinline__ void proj_load(
    uint32_t sOff, const __half* __restrict__ Ah, const __half* __restrict__ Al,
    const __half* __restrict__ B, int rowBase, int colBase, int k0, int tid, int two_term)
{
#pragma unroll
    for (int i = 0; i < 6; i++) {
        const int t = i >> 1;
        if (t == 1 && !two_term) continue;
        const int idx = ((i & 1) << 8) + tid;
        const int r = idx >> 2, c = idx & 3;
        const __half* src = (t == 0) ? Ah : (t == 1) ? Al : B;
        const int base = (t < 2) ? rowBase : colBase;
        cp16(sOff + t * TILEB + r * ROWB + c * 16,
             src + (size_t)(base + r) * HIDDEN_ + k0 + c * 8);
    }
}

__global__ void __launch_bounds__(256, 2) gemm_proj(
    const __half* __restrict__ Ah, const __half* __restrict__ Al,
    const __half* __restrict__ B, float* __restrict__ P32, __half* __restrict__ P16)
{
    extern __shared__ char smem[];
    const uint32_t sbase = smem_u32(smem);
    const int tid = threadIdx.x, w = tid >> 5, lane = tid & 31;
    const int rowBase = blockIdx.y * 128;
    const int colBase = blockIdx.x * 128;
    const int two_term = (colBase < GATE_C);
    const int wm = (w & 1) * 64, wn = (w >> 1) * 32;

    float acc[4][4][4];
#pragma unroll
    for (int mi = 0; mi < 4; mi++)
#pragma unroll
        for (int nj = 0; nj < 4; nj++)
#pragma unroll
            for (int e = 0; e < 4; e++) acc[mi][nj][e] = 0.f;

    const uint32_t aRowOff = (uint32_t)(wm + (lane & 15)) * ROWB + ((lane >> 4) & 1) * 16;
    const uint32_t bRowOff = (uint32_t)(wn + (lane & 7) + ((lane >> 4) & 1) * 8) * ROWB
                           + ((lane >> 3) & 1) * 16;

    const int KT = HIDDEN_ / GBK;   // 64
    proj_load(sbase,           Ah, Al, B, rowBase, colBase, 0,  tid, two_term); CP_COMMIT();
    proj_load(sbase + STAGE3B, Ah, Al, B, rowBase, colBase, 32, tid, two_term); CP_COMMIT();

    for (int kt = 0; kt < KT; kt++) {
        if (kt + 2 < KT) {
            proj_load(sbase + ((kt + 2) % 3) * STAGE3B, Ah, Al, B,
                      rowBase, colBase, (kt + 2) * GBK, tid, two_term);
            CP_COMMIT(); CP_WAIT(2);
        } else if (kt + 1 < KT) { CP_WAIT(1); } else { CP_WAIT(0); }
        __syncthreads();

        const uint32_t st = sbase + (kt % 3) * STAGE3B;
#pragma unroll
        for (int s = 0; s < 2; s++) {
            const uint32_t kb = s * 32;
            uint32_t bf[2][4];
#pragma unroll
            for (int pi = 0; pi < 2; pi++) {
                const uint32_t off = bRowOff + (uint32_t)pi * 16 * ROWB + kb;
                ldsm4(bf[pi][0], bf[pi][1], bf[pi][2], bf[pi][3], st + 2 * TILEB + off);
            }
#pragma unroll
            for (int mi = 0; mi < 4; mi++) {
                const uint32_t off = aRowOff + (uint32_t)mi * 16 * ROWB + kb;
                uint32_t ah[4], al[4];
                ldsm4(ah[0], ah[1], ah[2], ah[3], st + off);
                if (two_term) ldsm4(al[0], al[1], al[2], al[3], st + TILEB + off);
#pragma unroll
                for (int pi = 0; pi < 2; pi++)
#pragma unroll
                    for (int hf = 0; hf < 2; hf++) {
                        const int nj = pi * 2 + hf;
                        mmah(acc[mi][nj], ah, bf[pi][hf*2], bf[pi][hf*2+1]);
                        if (two_term) mmah(acc[mi][nj], al, bf[pi][hf*2], bf[pi][hf*2+1]);
                    }
            }
        }
        __syncthreads();
    }

    const int lr = lane >> 2, lc = (lane & 3) * 2;
#pragma unroll
    for (int mi = 0; mi < 4; mi++)
#pragma unroll
        for (int nj = 0; nj < 4; nj++) {
            const int r0 = rowBase + wm + mi * 16 + lr;
            const int cg = colBase + wn + nj * 8 + lc;
            if (cg < SPLITC) {
                *(float2*)(P32 + (size_t)r0 * SPLITC + cg)
                    = make_float2(acc[mi][nj][0], acc[mi][nj][1]);
                *(float2*)(P32 + (size_t)(r0 + 8) * SPLITC + cg)
                    = make_float2(acc[mi][nj][2], acc[mi][nj][3]);
            } else {
                const int cc = cg - SPLITC;
                *(__half2*)(P16 + (size_t)r0 * SPLITC + cc)
                    = __half2(__float2half(acc[mi][nj][0]), __float2half(acc[mi][nj][1]));
                *(__half2*)(P16 + (size_t)(r0 + 8) * SPLITC + cc)
                    = __half2(__float2half(acc[mi][nj][2]), __float2half(acc[mi][nj][3]));
            }
        }
}

// =================== Wo GEMM: A single fp16, B split fp16 (2-term) ===============
__global__ void __launch_bounds__(256, 2) gemm_wo(
    const __half* __restrict__ A, const __half* __restrict__ Bh,
    const __half* __restrict__ Bl, float* __restrict__ C)
{
    extern __shared__ char smem[];
    const uint32_t sbase = smem_u32(smem);
    const int tid = threadIdx.x, w = tid >> 5, lane = tid & 31;
    const int rowBase = blockIdx.y * 128;
    const int colBase = blockIdx.x * 128;
    const int wm = (w & 1) * 64, wn = (w >> 1) * 32;
    const int K = QDIM;            // 4096
    const int N = HIDDEN_;         // 2048

    float acc[4][4][4];
#pragma unroll
    for (int mi = 0; mi < 4; mi++)
#pragma unroll
        for (int nj = 0; nj < 4; nj++)
#pragma unroll
            for (int e = 0; e < 4; e++) acc[mi][nj][e] = 0.f;

    const uint32_t aRowOff = (uint32_t)(wm + (lane & 15)) * ROWB + ((lane >> 4) & 1) * 16;
    const uint32_t bRowOff = (uint32_t)(wn + (lane & 7) + ((lane >> 4) & 1) * 8) * ROWB
                           + ((lane >> 3) & 1) * 16;

    const int KT = K / GBK;   // 128
    // loader: tiles A(0), Bh(1), Bl(2)
#define WO_LOAD(sOff, k0) do { \
    _Pragma("unroll") \
    for (int i = 0; i < 6; i++) { \
        const int t = i >> 1; \
        const int idx = ((i & 1) << 8) + tid; \
        const int r = idx >> 2, c = idx & 3; \
        const __half* src = (t == 0) ? A : (t == 1) ? Bh : Bl; \
        const int base = (t == 0) ? rowBase : colBase; \
        cp16((sOff) + t * TILEB + r * ROWB + c * 16, \
             src + (size_t)(base + r) * K + (k0) + c * 8); \
    } } while (0)

    WO_LOAD(sbase, 0);            CP_COMMIT();
    WO_LOAD(sbase + STAGE3B, 32); CP_COMMIT();

    for (int kt = 0; kt < KT; kt++) {
        if (kt + 2 < KT) {
            WO_LOAD(sbase + ((kt + 2) % 3) * STAGE3B, (kt + 2) * GBK);
            CP_COMMIT(); CP_WAIT(2);
        } else if (kt + 1 < KT) { CP_WAIT(1); } else { CP_WAIT(0); }
        __syncthreads();

        const uint32_t st = sbase + (kt % 3) * STAGE3B;
#pragma unroll
        for (int s = 0; s < 2; s++) {
            const uint32_t kb = s * 32;
            uint32_t bh[2][4], bl[2][4];
#pragma unroll
            for (int pi = 0; pi < 2; pi++) {
                const uint32_t off = bRowOff + (uint32_t)pi * 16 * ROWB + kb;
                ldsm4(bh[pi][0], bh[pi][1], bh[pi][2], bh[pi][3], st + 1 * TILEB + off);
                ldsm4(bl[pi][0], bl[pi][1], bl[pi][2], bl[pi][3], st + 2 * TILEB + off);
            }
#pragma unroll
            for (int mi = 0; mi < 4; mi++) {
                const uint32_t off = aRowOff + (uint32_t)mi * 16 * ROWB + kb;
                uint32_t af[4];
                ldsm4(af[0], af[1], af[2], af[3], st + off);
#pragma unroll
                for (int pi = 0; pi < 2; pi++)
#pragma unroll
                    for (int hf = 0; hf < 2; hf++) {
                        const int nj = pi * 2 + hf;
                        mmah(acc[mi][nj], af, bh[pi][hf*2], bh[pi][hf*2+1]);
                        mmah(acc[mi][nj], af, bl[pi][hf*2], bl[pi][hf*2+1]);
                    }
            }
        }
        __syncthreads();
    }

    const int lr = lane >> 2, lc = (lane & 3) * 2;
#pragma unroll
    for (int mi = 0; mi < 4; mi++)
#pragma unroll
        for (int nj = 0; nj < 4; nj++) {
            const int r0 = rowBase + wm + mi * 16 + lr;
            const int cg = colBase + wn + nj * 8 + lc;
            *(float2*)(C + (size_t)r0 * N + cg)       = make_float2(acc[mi][nj][0], acc[mi][nj][1]);
            *(float2*)(C + (size_t)(r0 + 8) * N + cg) = make_float2(acc[mi][nj][2], acc[mi][nj][3]);
        }
#undef WO_LOAD
}

// ---------------- fused RMSNorm + partial RoPE (fp32 in, fp16 [hi/lo] out) ------
__global__ void __launch_bounds__(256) rmsnorm_rope_f16(
    const float* __restrict__ X, int xs, const float* __restrict__ w,
    const float* __restrict__ cosb, const float* __restrict__ sinb,
    __half* __restrict__ H, __half* __restrict__ L, int os)
{
    const int t = blockIdx.x, h = blockIdx.y, d = threadIdx.x;
    float x = X[(size_t)t * xs + h * HDIM + d];

    float ss = x * x;
#pragma unroll
    for (int off = 16; off; off >>= 1) ss += __shfl_xor_sync(0xffffffffu, ss, off);
    __shared__ float red[8];
    if ((d & 31) == 0) red[d >> 5] = ss;
    __syncthreads();
    float sum = red[0]+red[1]+red[2]+red[3]+red[4]+red[5]+red[6]+red[7];
    float inv = rsqrtf(sum * (1.f/256.f) + 1e-6f);
    float n = x * inv * w[d];

    __shared__ float sn[ROT];
    if (d < ROT) sn[d] = n;
    __syncthreads();

    float out = n;
    if (d < 32) {
        float c = cosb[t*ROT + d], s = sinb[t*ROT + d];
        out = n * c - sn[d + 32] * s;
    } else if (d < ROT) {
        float c = cosb[t*ROT + d], s = sinb[t*ROT + d];
        out = n * c + sn[d - 32] * s;
    }
    const size_t idx = (size_t)t * os + h * HDIM + d;
    __half hv = __float2half(out);
    H[idx] = hv;
    if (L) L[idx] = __float2half(out - __half2float(hv));
}

// =================== flash attention (fp16, K-split 2-term, dbl-buffered KV) ====
#define FROWB   528
#define FQ      0
#define FKH(b)  ((uint32_t)(128 + (b)*96) * FROWB)
#define FKL(b)  ((uint32_t)(160 + (b)*96) * FROWB)
#define FV(b)   ((uint32_t)(192 + (b)*96) * FROWB)
#define FSMEM   (320 * FROWB)          // 168960

__global__ void __launch_bounds__(256, 1) flash_f16(
    const __half* __restrict__ Qf, const __half* __restrict__ Kh,
    const __half* __restrict__ Kl, const __half* __restrict__ P16,
    __half* __restrict__ Attn)
{
    extern __shared__ char smem[];
    const uint32_t sb = smem_u32(smem);
    const int tid = threadIdx.x, warp = tid >> 5, lane = tid & 31;
    const int qblk = blockIdx.x;
    const int b    = blockIdx.y >> 1;
    const int kvh  = blockIdx.y & 1;
    const int qbase = qblk * 16;
    const int h    = kvh * 8 + warp;

    // Q tile: 8 heads x 16 rows x 256d fp16 (single)
    for (int i = tid; i < 4096; i += 256) {
        const int r = i >> 5, c = i & 31;
        const size_t src = (size_t)(b * 2048 + qbase + (r & 15)) * QDIM
                         + (kvh * 8 + (r >> 4)) * HDIM + c * 8;
        cp16(sb + FQ + (uint32_t)r * FROWB + c * 16, Qf + src);
    }
    CP_COMMIT();

#define KV_LOAD(buf, j0) do { \
    for (int i = tid; i < 1024; i += 256) { \
        const int r = i >> 5, c = i & 31; \
        const int kr = min((j0) + r, 2047); \
        const size_t ks = (size_t)(b * 2048 + kr) * KVDIM + kvh * HDIM + c * 8; \
        const size_t vs = (size_t)(b * 2048 + kr) * SPLITC + kvh * HDIM + c * 8; \
        const uint32_t dd = (uint32_t)r * FROWB + c * 16; \
        cp16(sb + FKH(buf) + dd, Kh + ks); \
        cp16(sb + FKL(buf) + dd, Kl + ks); \
        cp16(sb + FV(buf)  + dd, P16 + vs); \
    } } while (0)

    KV_LOAD(0, 0);
    CP_COMMIT();

    float o[32][4];
#pragma unroll
    for (int nt = 0; nt < 32; nt++)
#pragma unroll
        for (int e = 0; e < 4; e++) o[nt][e] = 0.f;
    float m0 = -1e30f, m1 = -1e30f, l0 = 0.f, l1 = 0.f;

    const int g  = lane >> 2;
    const int cb = (lane & 3) * 2;

    const uint32_t qAddr = sb + FQ + (uint32_t)(warp * 16 + (lane & 15)) * FROWB
                         + ((lane >> 4) & 1) * 16;
    const uint32_t kOff  = (uint32_t)((lane & 7) + ((lane >> 4) & 1) * 8) * FROWB
                         + ((lane >> 3) & 1) * 16;
    const uint32_t vOff  = (uint32_t)(lane & 15) * FROWB + (lane >> 4) * 16;

    const int ntiles = ((qbase + 15) >> 5) + 1;
    CP_WAIT(0);
    __syncthreads();

    for (int it = 0; it < ntiles; it++) {
        const int j0 = it * 32;
        const int buf = it & 1;
        if (it + 1 < ntiles) { KV_LOAD(buf ^ 1, j0 + 32); CP_COMMIT(); CP_WAIT(1); }
        else                 { CP_WAIT(0); }
        __syncthreads();

        // S = Q K^T : 2-term (Q·Kh + Q·Kl)
        float S[4][4];
#pragma unroll
        for (int nt = 0; nt < 4; nt++)
#pragma unroll
            for (int e = 0; e < 4; e++) S[nt][e] = 0.f;

        const uint32_t kh = sb + FKH(buf) + kOff;
        const uint32_t kl = sb + FKL(buf) + kOff;
#pragma unroll
        for (int ks = 0; ks < 16; ks++) {
            uint32_t q[4], k0h[4], k1h[4], k0l[4], k1l[4];
            ldsm4(q[0], q[1], q[2], q[3], qAddr + ks * 32);
            ldsm4(k0h[0], k0h[1], k0h[2], k0h[3], kh + ks * 32);
            ldsm4(k1h[0], k1h[1], k1h[2], k1h[3], kh + 16 * FROWB + ks * 32);
            ldsm4(k0l[0], k0l[1], k0l[2], k0l[3], kl + ks * 32);
            ldsm4(k1l[0], k1l[1], k1l[2], k1l[3], kl + 16 * FROWB + ks * 32);
            mmah(S[0], q, k0h[0], k0h[1]);  mmah(S[0], q, k0l[0], k0l[1]);
            mmah(S[1], q, k0h[2], k0h[3]);  mmah(S[1], q, k0l[2], k0l[3]);
            mmah(S[2], q, k1h[0], k1h[1]);  mmah(S[2], q, k1l[0], k1l[1]);
            mmah(S[3], q, k1h[2], k1h[3]);  mmah(S[3], q, k1l[2], k1l[3]);
        }

        if (it == ntiles - 1) {
#pragma unroll
            for (int nt = 0; nt < 4; nt++)
#pragma unroll
                for (int e = 0; e < 4; e++) {
                    const int row = qbase + g + (e >> 1) * 8;
                    const int col = j0 + nt * 8 + cb + (e & 1);
                    if (col > row) S[nt][e] = -1e30f;
                }
        }

        float tm0 = -1e30f, tm1 = -1e30f;
#pragma unroll
        for (int nt = 0; nt < 4; nt++) {
            tm0 = fmaxf(tm0, fmaxf(S[nt][0], S[nt][1]));
            tm1 = fmaxf(tm1, fmaxf(S[nt][2], S[nt][3]));
        }
        tm0 = fmaxf(tm0, __shfl_xor_sync(0xffffffffu, tm0, 1));
        tm0 = fmaxf(tm0, __shfl_xor_sync(0xffffffffu, tm0, 2));
        tm1 = fmaxf(tm1, __shfl_xor_sync(0xffffffffu, tm1, 1));
        tm1 = fmaxf(tm1, __shfl_xor_sync(0xffffffffu, tm1, 2));
        const float nm0 = fmaxf(m0, tm0), nm1 = fmaxf(m1, tm1);
        const float c0 = ex2((m0 - nm0) * K2EXP);
        const float c1 = ex2((m1 - nm1) * K2EXP);
        m0 = nm0; m1 = nm1;
        l0 *= c0;  l1 *= c1;
        if (__any_sync(0xffffffffu, (c0 < 1.f) || (c1 < 1.f))) {
#pragma unroll
            for (int nt = 0; nt < 32; nt++) {
                o[nt][0] *= c0; o[nt][1] *= c0;
                o[nt][2] *= c1; o[nt][3] *= c1;
            }
        }
#pragma unroll
        for (int nt = 0; nt < 4; nt++) {
            S[nt][0] = ex2((S[nt][0] - m0) * K2EXP);
            S[nt][1] = ex2((S[nt][1] - m0) * K2EXP);
            S[nt][2] = ex2((S[nt][2] - m1) * K2EXP);
            S[nt][3] = ex2((S[nt][3] - m1) * K2EXP);
            l0 += S[nt][0] + S[nt][1];
            l1 += S[nt][2] + S[nt][3];
        }

        // P fragments (fp16 hi/lo)
        uint32_t pah[2][4], pal[2][4];
#pragma unroll
        for (int ks2 = 0; ks2 < 2; ks2++) {
            const int t0 = ks2 * 2, t1 = t0 + 1;
            const float pv[8] = { S[t0][0], S[t0][1], S[t0][2], S[t0][3],
                                  S[t1][0], S[t1][1], S[t1][2], S[t1][3] };
            float hv[8], lv[8];
#pragma unroll
            for (int e = 0; e < 8; e++) {
                __half hb = __float2half(pv[e]);
                hv[e] = __half2float(hb);
                lv[e] = pv[e] - hv[e];
            }
            pah[ks2][0] = pack_f16(hv[0], hv[1]); pah[ks2][1] = pack_f16(hv[2], hv[3]);
            pah[ks2][2] = pack_f16(hv[4], hv[5]); pah[ks2][3] = pack_f16(hv[6], hv[7]);
            pal[ks2][0] = pack_f16(lv[0], lv[1]); pal[ks2][1] = pack_f16(lv[2], lv[3]);
            pal[ks2][2] = pack_f16(lv[4], lv[5]); pal[ks2][3] = pack_f16(lv[6], lv[7]);
        }

        // O += P V (P split, V single)
#pragma unroll
        for (int ks2 = 0; ks2 < 2; ks2++) {
            const uint32_t vb = sb + FV(buf) + vOff + (uint32_t)ks2 * 16 * FROWB;
#pragma unroll
            for (int g16 = 0; g16 < 16; g16++) {
                uint32_t v[4];
                ldsm4t(v[0], v[1], v[2], v[3], vb + g16 * 32);
                const int n0 = g16 * 2, n1 = n0 + 1;
                mmah(o[n0], pah[ks2], v[0], v[1]);
                mmah(o[n0], pal[ks2], v[0], v[1]);
                mmah(o[n1], pah[ks2], v[2], v[3]);
                mmah(o[n1], pal[ks2], v[2], v[3]);
            }
        }
        __syncthreads();
    }

    l0 += __shfl_xor_sync(0xffffffffu, l0, 1);
    l0 += __shfl_xor_sync(0xffffffffu, l0, 2);
    l1 += __shfl_xor_sync(0xffffffffu, l1, 1);
    l1 += __shfl_xor_sync(0xffffffffu, l1, 2);
    const float inv0 = frcp(l0), inv1 = frcp(l1);

#pragma unroll
    for (int nt = 0; nt < 32; nt++) {
#pragma unroll
        for (int e = 0; e < 4; e++) {
            const int row = qbase + g + (e >> 1) * 8;
            const int d   = nt * 8 + cb + (e & 1);
            const size_t tq = (size_t)(b * 2048 + row);
            const float gt  = __half2float(P16[tq * SPLITC + 512 + h * HDIM + d]);
            const float sig = frcp(1.f + ex2(-gt * 1.4426950f));
            const float val = o[nt][e] * ((e < 2) ? inv0 : inv1) * sig;
            Attn[tq * QDIM + h * HDIM + d] = __float2half(val);
        }
    }
#undef KV_LOAD
}

// ---------------- launcher ------------------------------------------------------
extern "C" void kernel_launch(void* const* d_in, const int* in_sizes, int n_in,
                              void* d_out, int out_size)
{
    const float* hidden = (const float*)d_in[0];
    const float* cosb   = (const float*)d_in[1];
    const float* sinb   = (const float*)d_in[2];
    const float* Wq     = (const float*)d_in[3];
    const float* Wk     = (const float*)d_in[4];
    const float* Wv     = (const float*)d_in[5];
    const float* Wo     = (const float*)d_in[6];
    const float* qnw    = (const float*)d_in[7];
    const float* knw    = (const float*)d_in[8];
    float* out = (float*)d_out;

    __half *hidH, *hidL, *Wcat, *WoH, *WoL, *P16, *Qf, *KH, *KL, *Attn;
    float *P32;
    cudaGetSymbolAddress((void**)&hidH, g_hidH);
    cudaGetSymbolAddress((void**)&hidL, g_hidL);
    cudaGetSymbolAddress((void**)&Wcat, g_Wcat);
    cudaGetSymbolAddress((void**)&WoH,  g_WoH);
    cudaGetSymbolAddress((void**)&WoL,  g_WoL);
    cudaGetSymbolAddress((void**)&P32,  g_P32);
    cudaGetSymbolAddress((void**)&P16,  g_P16);
    cudaGetSymbolAddress((void**)&Qf,   g_Qf);
    cudaGetSymbolAddress((void**)&KH,   g_KH);
    cudaGetSymbolAddress((void**)&KL,   g_KL);
    cudaGetSymbolAddress((void**)&Attn, g_Attn);

    cudaFuncSetAttribute(gemm_proj, cudaFuncAttributeMaxDynamicSharedMemorySize, PSMEM);
    cudaFuncSetAttribute(gemm_wo,   cudaFuncAttributeMaxDynamicSharedMemorySize, PSMEM);
    cudaFuncSetAttribute(flash_f16, cudaFuncAttributeMaxDynamicSharedMemorySize, FSMEM);

    // 0) conversions
    {
        int n4 = TOKENS * HIDDEN_ / 4;
        split_f16<<<(n4 + 255) / 256, 256>>>(hidden, hidH, hidL, n4);
        int nw = PROJ_N * (HIDDEN_ / 4);
        conv_wcat<<<(nw + 255) / 256, 256>>>(Wq, Wk, Wv, Wcat);
        n4 = HIDDEN_ * QDIM / 4;
        split_f16<<<(n4 + 255) / 256, 256>>>(Wo, WoH, WoL, n4);
    }
    // 1) fused QKV+gate projection
    gemm_proj<<<dim3(PROJ_N / 128, TOKENS / 128), 256, PSMEM>>>(hidH, hidL, Wcat, P32, P16);
    // 2) RMSNorm + RoPE
    rmsnorm_rope_f16<<<dim3(TOKENS, NHEADS), 256>>>(P32, SPLITC, qnw, cosb, sinb,
                                                    Qf, nullptr, QDIM);
    rmsnorm_rope_f16<<<dim3(TOKENS, NKV), 256>>>(P32 + QDIM, SPLITC, knw, cosb, sinb,
                                                 KH, KL, KVDIM);
    // 3) flash attention + sigmoid gate
    flash_f16<<<dim3(2048 / 16, 4), 256, FSMEM>>>(Qf, KH, KL, P16, Attn);
    // 4) output projection
    gemm_wo<<<dim3(HIDDEN_ / 128, TOKENS / 128), 256, PSMEM>>>(Attn, WoH, WoL, out);
}

// round 17
// speedup vs baseline: 10.0605x; 1.3005x over previous
#include <cuda_runtime.h>
#include <cuda_fp16.h>
#include <math.h>
#include <stdint.h>

// Problem constants
#define TOKENS   4096          // B*S
#define HIDDEN_  2048
#define NHEADS   16
#define NKV      2
#define HDIM     256
#define QDIM     4096
#define KVDIM    512
#define ROT      64
#define K2EXP    0.09016844f   // (1/sqrt(256)) * log2(e)

// fused projection layout: cols [0,4096) Q | [4096,4608) K | [4608,5120) V | [5120,9216) gate
#define PROJ_N   9216
#define SPLITC   4608          // fp32-out columns below, fp16-out above

// ---------------- scratch ----------------
__device__ __half g_hidF[(size_t)TOKENS * HIDDEN_];
__device__ __half g_Wcat[(size_t)PROJ_N * HIDDEN_];     // concat Q|K|V|gate weights, fp16
__device__ __half g_WoF[(size_t)HIDDEN_ * QDIM];
__device__ float  g_P32[(size_t)TOKENS * SPLITC];       // Q,K raw (pre-norm) fp32
__device__ __half g_P16[(size_t)TOKENS * SPLITC];       // cols 0..511 = V, 512..4607 = gate
__device__ __half g_Qf [(size_t)TOKENS * QDIM];         // normalized+roped Q, fp16
__device__ __half g_KH [(size_t)TOKENS * KVDIM];        // normalized+roped K hi
__device__ __half g_KL [(size_t)TOKENS * KVDIM];        // K lo
__device__ __half g_Attn[(size_t)TOKENS * QDIM];        // gated attention out, fp16

// =================== helpers ===================
__device__ __forceinline__ uint32_t smem_u32(const void* p) {
    uint32_t a;
    asm("{ .reg .u64 t; cvta.to.shared.u64 t, %1; cvt.u32.u64 %0, t; }" : "=r"(a) : "l"(p));
    return a;
}
__device__ __forceinline__ void cp16(uint32_t s, const void* g) {
    asm volatile("cp.async.cg.shared.global [%0], [%1], 16;" :: "r"(s), "l"(g));
}
#define CP_COMMIT() asm volatile("cp.async.commit_group;" ::: "memory")
#define CP_WAIT(n)  asm volatile("cp.async.wait_group %0;" :: "n"(n) : "memory")

__device__ __forceinline__ void ldsm4(uint32_t& r0, uint32_t& r1, uint32_t& r2, uint32_t& r3,
                                      uint32_t addr) {
    asm volatile("ldmatrix.sync.aligned.m8n8.x4.shared.b16 {%0,%1,%2,%3}, [%4];"
        : "=r"(r0), "=r"(r1), "=r"(r2), "=r"(r3) : "r"(addr));
}
__device__ __forceinline__ void ldsm4t(uint32_t& r0, uint32_t& r1, uint32_t& r2, uint32_t& r3,
                                       uint32_t addr) {
    asm volatile("ldmatrix.sync.aligned.m8n8.x4.trans.shared.b16 {%0,%1,%2,%3}, [%4];"
        : "=r"(r0), "=r"(r1), "=r"(r2), "=r"(r3) : "r"(addr));
}
__device__ __forceinline__ void mmah(float* d, const uint32_t* a, uint32_t b0, uint32_t b1) {
    asm volatile("mma.sync.aligned.m16n8k16.row.col.f32.f16.f16.f32 "
        "{%0,%1,%2,%3}, {%4,%5,%6,%7}, {%8,%9}, {%0,%1,%2,%3};"
        : "+f"(d[0]), "+f"(d[1]), "+f"(d[2]), "+f"(d[3])
        : "r"(a[0]), "r"(a[1]), "r"(a[2]), "r"(a[3]), "r"(b0), "r"(b1));
}
__device__ __forceinline__ float ex2(float x) {
    float r; asm("ex2.approx.f32 %0, %1;" : "=f"(r) : "f"(x)); return r;
}
__device__ __forceinline__ float frcp(float x) {
    float r; asm("rcp.approx.f32 %0, %1;" : "=f"(r) : "f"(x)); return r;
}
__device__ __forceinline__ uint32_t pack_f16(float lo, float hi) {
    uint32_t r;
    asm("cvt.rn.f16x2.f32 %0, %1, %2;" : "=r"(r) : "f"(hi), "f"(lo));
    return r;
}

// =================== conversion kernels ===================
__global__ void __launch_bounds__(256) conv_f16(
    const float* __restrict__ X, __half* __restrict__ F, int n4)
{
    int i = blockIdx.x * 256 + threadIdx.x;
    if (i >= n4) return;
    float4 x = ((const float4*)X)[i];
    ((__half2*)F)[i*2]   = __half2(__float2half(x.x), __float2half(x.y));
    ((__half2*)F)[i*2+1] = __half2(__float2half(x.z), __float2half(x.w));
}

// build concatenated weight matrix [9216][2048] fp16 (Q head-major | K | V | gate head-major)
__global__ void __launch_bounds__(256) conv_wcat(
    const float* __restrict__ Wq, const float* __restrict__ Wk,
    const float* __restrict__ Wv, __half* __restrict__ Wcat)
{
    int i = blockIdx.x * 256 + threadIdx.x;
    if (i >= PROJ_N * (HIDDEN_/4)) return;
    const int n = i >> 9, c = i & 511;
    const float* base;
    if (n < 4096)       base = Wq + (size_t)(((n >> 8) << 9) + (n & 255)) * HIDDEN_;
    else if (n < 4608)  base = Wk + (size_t)(n - 4096) * HIDDEN_;
    else if (n < 5120)  base = Wv + (size_t)(n - 4608) * HIDDEN_;
    else { int m = n - 5120; base = Wq + (size_t)(((m >> 8) << 9) + 256 + (m & 255)) * HIDDEN_; }
    float4 x = ((const float4*)base)[c];
    __half2* dst = (__half2*)(Wcat + (size_t)n * HIDDEN_);
    dst[c*2]   = __half2(__float2half(x.x), __float2half(x.y));
    dst[c*2+1] = __half2(__float2half(x.z), __float2half(x.w));
}

// =================== unified 1-term fp16 GEMM ===================
// C[M,N] = A[M,K] x B[N,K]^T, both single fp16. 128x128 tile, BK=32, 3-stage.
// Epilogue: cols < splitc -> C32 (fp32), cols >= splitc -> C16 (fp16), row stride ostride.
#define GBK     32
#define ROWB    80
#define TILEB   (128 * ROWB)       // 10240
#define STG2B   (2 * TILEB)        // A, B
#define GSMEM1  (3 * STG2B)        // 61440, 3 stages

__global__ void __launch_bounds__(256, 2) gemm_1t(
    const __half* __restrict__ A, const __half* __restrict__ B,
    float* __restrict__ C32, __half* __restrict__ C16,
    int K, int splitc, int ostride)
{
    extern __shared__ char smem[];
    const uint32_t sbase = smem_u32(smem);
    const int tid = threadIdx.x, w = tid >> 5, lane = tid & 31;
    const int rowBase = blockIdx.y * 128;
    const int colBase = blockIdx.x * 128;
    const int wm = (w & 1) * 64, wn = (w >> 1) * 32;

    float acc[4][4][4];
#pragma unroll
    for (int mi = 0; mi < 4; mi++)
#pragma unroll
        for (int nj = 0; nj < 4; nj++)
#pragma unroll
            for (int e = 0; e < 4; e++) acc[mi][nj][e] = 0.f;

    const uint32_t aRowOff = (uint32_t)(wm + (lane & 15)) * ROWB + ((lane >> 4) & 1) * 16;
    const uint32_t bRowOff = (uint32_t)(wn + (lane & 7) + ((lane >> 4) & 1) * 8) * ROWB
                           + ((lane >> 3) & 1) * 16;

#define G1_LOAD(sOff, k0) do { \
    _Pragma("unroll") \
    for (int i = 0; i < 4; i++) { \
        const int t = i >> 1; \
        const int idx = ((i & 1) << 8) + tid; \
        const int r = idx >> 2, c = idx & 3; \
        const __half* src = t ? B : A; \
        const int base = t ? colBase : rowBase; \
        cp16((sOff) + t * TILEB + r * ROWB + c * 16, \
             src + (size_t)(base + r) * K + (k0) + c * 8); \
    } } while (0)

    const int KT = K / GBK;
    G1_LOAD(sbase, 0);           CP_COMMIT();
    G1_LOAD(sbase + STG2B, 32);  CP_COMMIT();

    for (int kt = 0; kt < KT; kt++) {
        if (kt + 2 < KT) {
            G1_LOAD(sbase + ((kt + 2) % 3) * STG2B, (kt + 2) * GBK);
            CP_COMMIT(); CP_WAIT(2);
        } else if (kt + 1 < KT) { CP_WAIT(1); } else { CP_WAIT(0); }
        __syncthreads();

        const uint32_t st = sbase + (kt % 3) * STG2B;
#pragma unroll
        for (int s = 0; s < 2; s++) {
            const uint32_t kb = s * 32;
            uint32_t bf[2][4];
#pragma unroll
            for (int pi = 0; pi < 2; pi++) {
                const uint32_t off = bRowOff + (uint32_t)pi * 16 * ROWB + kb;
                ldsm4(bf[pi][0], bf[pi][1], bf[pi][2], bf[pi][3], st + TILEB + off);
            }
#pragma unroll
            for (int mi = 0; mi < 4; mi++) {
                const uint32_t off = aRowOff + (uint32_t)mi * 16 * ROWB + kb;
                uint32_t af[4];
                ldsm4(af[0], af[1], af[2], af[3], st + off);
#pragma unroll
                for (int pi = 0; pi < 2; pi++)
#pragma unroll
                    for (int hf = 0; hf < 2; hf++)
                        mmah(acc[mi][pi*2+hf], af, bf[pi][hf*2], bf[pi][hf*2+1]);
            }
        }
        __syncthreads();
    }

    const int lr = lane >> 2, lc = (lane & 3) * 2;
#pragma unroll
    for (int mi = 0; mi < 4; mi++)
#pragma unroll
        for (int nj = 0; nj < 4; nj++) {
            const int r0 = rowBase + wm + mi * 16 + lr;
            const int cg = colBase + wn + nj * 8 + lc;
            if (cg < splitc) {
                *(float2*)(C32 + (size_t)r0 * ostride + cg)
                    = make_float2(acc[mi][nj][0], acc[mi][nj][1]);
                *(float2*)(C32 + (size_t)(r0 + 8) * ostride + cg)
                    = make_float2(acc[mi][nj][2], acc[mi][nj][3]);
            } else {
                const int cc = cg - splitc;
                *(__half2*)(C16 + (size_t)r0 * ostride + cc)
                    = __half2(__float2half(acc[mi][nj][0]), __float2half(acc[mi][nj][1]));
                *(__half2*)(C16 + (size_t)(r0 + 8) * ostride + cc)
                    = __half2(__float2half(acc[mi][nj][2]), __float2half(acc[mi][nj][3]));
            }
        }
#undef G1_LOAD
}

// ---------------- fused RMSNorm + partial RoPE (fp32 in, fp16 [hi/lo] out) ------
__global__ void __launch_bounds__(256) rmsnorm_rope_f16(
    const float* __restrict__ X, int xs, const float* __restrict__ w,
    const float* __restrict__ cosb, const float* __restrict__ sinb,
    __half* __restrict__ H, __half* __restrict__ L, int os)
{
    const int t = blockIdx.x, h = blockIdx.y, d = threadIdx.x;
    float x = X[(size_t)t * xs + h * HDIM + d];

    float ss = x * x;
#pragma unroll
    for (int off = 16; off; off >>= 1) ss += __shfl_xor_sync(0xffffffffu, ss, off);
    __shared__ float red[8];
    if ((d & 31) == 0) red[d >> 5] = ss;
    __syncthreads();
    float sum = red[0]+red[1]+red[2]+red[3]+red[4]+red[5]+red[6]+red[7];
    float inv = rsqrtf(sum * (1.f/256.f) + 1e-6f);
    float n = x * inv * w[d];

    __shared__ float sn[ROT];
    if (d < ROT) sn[d] = n;
    __syncthreads();

    float out = n;
    if (d < 32) {
        float c = cosb[t*ROT + d], s = sinb[t*ROT + d];
        out = n * c - sn[d + 32] * s;
    } else if (d < ROT) {
        float c = cosb[t*ROT + d], s = sinb[t*ROT + d];
        out = n * c + sn[d - 32] * s;
    }
    const size_t idx = (size_t)t * os + h * HDIM + d;
    __half hv = __float2half(out);
    H[idx] = hv;
    if (L) L[idx] = __float2half(out - __half2float(hv));
}

// =================== flash attention (fp16, K-split 2-term, dbl-buffered KV) ====
#define FROWB   528
#define FQ      0
#define FKH(b)  ((uint32_t)(128 + (b)*96) * FROWB)
#define FKL(b)  ((uint32_t)(160 + (b)*96) * FROWB)
#define FV(b)   ((uint32_t)(192 + (b)*96) * FROWB)
#define FSMEM   (320 * FROWB)          // 168960

__global__ void __launch_bounds__(256, 1) flash_f16(
    const __half* __restrict__ Qf, const __half* __restrict__ Kh,
    const __half* __restrict__ Kl, const __half* __restrict__ P16,
    __half* __restrict__ Attn)
{
    extern __shared__ char smem[];
    const uint32_t sb = smem_u32(smem);
    const int tid = threadIdx.x, warp = tid >> 5, lane = tid & 31;
    const int qblk = blockIdx.x;
    const int b    = blockIdx.y >> 1;
    const int kvh  = blockIdx.y & 1;
    const int qbase = qblk * 16;
    const int h    = kvh * 8 + warp;

    for (int i = tid; i < 4096; i += 256) {
        const int r = i >> 5, c = i & 31;
        const size_t src = (size_t)(b * 2048 + qbase + (r & 15)) * QDIM
                         + (kvh * 8 + (r >> 4)) * HDIM + c * 8;
        cp16(sb + FQ + (uint32_t)r * FROWB + c * 16, Qf + src);
    }
    CP_COMMIT();

#define KV_LOAD(buf, j0) do { \
    for (int i = tid; i < 1024; i += 256) { \
        const int r = i >> 5, c = i & 31; \
        const int kr = min((j0) + r, 2047); \
        const size_t ks = (size_t)(b * 2048 + kr) * KVDIM + kvh * HDIM + c * 8; \
        const size_t vs = (size_t)(b * 2048 + kr) * SPLITC + kvh * HDIM + c * 8; \
        const uint32_t dd = (uint32_t)r * FROWB + c * 16; \
        cp16(sb + FKH(buf) + dd, Kh + ks); \
        cp16(sb + FKL(buf) + dd, Kl + ks); \
        cp16(sb + FV(buf)  + dd, P16 + vs); \
    } } while (0)

    KV_LOAD(0, 0);
    CP_COMMIT();

    float o[32][4];
#pragma unroll
    for (int nt = 0; nt < 32; nt++)
#pragma unroll
        for (int e = 0; e < 4; e++) o[nt][e] = 0.f;
    float m0 = -1e30f, m1 = -1e30f, l0 = 0.f, l1 = 0.f;

    const int g  = lane >> 2;
    const int cb = (lane & 3) * 2;

    const uint32_t qAddr = sb + FQ + (uint32_t)(warp * 16 + (lane & 15)) * FROWB
                         + ((lane >> 4) & 1) * 16;
    const uint32_t kOff  = (uint32_t)((lane & 7) + ((lane >> 4) & 1) * 8) * FROWB
                         + ((lane >> 3) & 1) * 16;
    const uint32_t vOff  = (uint32_t)(lane & 15) * FROWB + (lane >> 4) * 16;

    const int ntiles = ((qbase + 15) >> 5) + 1;
    CP_WAIT(0);
    __syncthreads();

    for (int it = 0; it < ntiles; it++) {
        const int j0 = it * 32;
        const int buf = it & 1;
        if (it + 1 < ntiles) { KV_LOAD(buf ^ 1, j0 + 32); CP_COMMIT(); CP_WAIT(1); }
        else                 { CP_WAIT(0); }
        __syncthreads();

        float S[4][4];
#pragma unroll
        for (int nt = 0; nt < 4; nt++)
#pragma unroll
            for (int e = 0; e < 4; e++) S[nt][e] = 0.f;

        const uint32_t kh = sb + FKH(buf) + kOff;
        const uint32_t kl = sb + FKL(buf) + kOff;
#pragma unroll
        for (int ks = 0; ks < 16; ks++) {
            uint32_t q[4], k0h[4], k1h[4], k0l[4], k1l[4];
            ldsm4(q[0], q[1], q[2], q[3], qAddr + ks * 32);
            ldsm4(k0h[0], k0h[1], k0h[2], k0h[3], kh + ks * 32);
            ldsm4(k1h[0], k1h[1], k1h[2], k1h[3], kh + 16 * FROWB + ks * 32);
            ldsm4(k0l[0], k0l[1], k0l[2], k0l[3], kl + ks * 32);
            ldsm4(k1l[0], k1l[1], k1l[2], k1l[3], kl + 16 * FROWB + ks * 32);
            mmah(S[0], q, k0h[0], k0h[1]);  mmah(S[0], q, k0l[0], k0l[1]);
            mmah(S[1], q, k0h[2], k0h[3]);  mmah(S[1], q, k0l[2], k0l[3]);
            mmah(S[2], q, k1h[0], k1h[1]);  mmah(S[2], q, k1l[0], k1l[1]);
            mmah(S[3], q, k1h[2], k1h[3]);  mmah(S[3], q, k1l[2], k1l[3]);
        }

        if (it == ntiles - 1) {
#pragma unroll
            for (int nt = 0; nt < 4; nt++)
#pragma unroll
                for (int e = 0; e < 4; e++) {
                    const int row = qbase + g + (e >> 1) * 8;
                    const int col = j0 + nt * 8 + cb + (e & 1);
                    if (col > row) S[nt][e] = -1e30f;
                }
        }

        float tm0 = -1e30f, tm1 = -1e30f;
#pragma unroll
        for (int nt = 0; nt < 4; nt++) {
            tm0 = fmaxf(tm0, fmaxf(S[nt][0], S[nt][1]));
            tm1 = fmaxf(tm1, fmaxf(S[nt][2], S[nt][3]));
        }
        tm0 = fmaxf(tm0, __shfl_xor_sync(0xffffffffu, tm0, 1));
        tm0 = fmaxf(tm0, __shfl_xor_sync(0xffffffffu, tm0, 2));
        tm1 = fmaxf(tm1, __shfl_xor_sync(0xffffffffu, tm1, 1));
        tm1 = fmaxf(tm1, __shfl_xor_sync(0xffffffffu, tm1, 2));
        const float nm0 = fmaxf(m0, tm0), nm1 = fmaxf(m1, tm1);
        const float c0 = ex2((m0 - nm0) * K2EXP);
        const float c1 = ex2((m1 - nm1) * K2EXP);
        m0 = nm0; m1 = nm1;
        l0 *= c0;  l1 *= c1;
        if (__any_sync(0xffffffffu, (c0 < 1.f) || (c1 < 1.f))) {
#pragma unroll
            for (int nt = 0; nt < 32; nt++) {
                o[nt][0] *= c0; o[nt][1] *= c0;
                o[nt][2] *= c1; o[nt][3] *= c1;
            }
        }
#pragma unroll
        for (int nt = 0; nt < 4; nt++) {
            S[nt][0] = ex2((S[nt][0] - m0) * K2EXP);
            S[nt][1] = ex2((S[nt][1] - m0) * K2EXP);
            S[nt][2] = ex2((S[nt][2] - m1) * K2EXP);
            S[nt][3] = ex2((S[nt][3] - m1) * K2EXP);
            l0 += S[nt][0] + S[nt][1];
            l1 += S[nt][2] + S[nt][3];
        }

        uint32_t pah[2][4], pal[2][4];
#pragma unroll
        for (int ks2 = 0; ks2 < 2; ks2++) {
            const int t0 = ks2 * 2, t1 = t0 + 1;
            const float pv[8] = { S[t0][0], S[t0][1], S[t0][2], S[t0][3],
                                  S[t1][0], S[t1][1], S[t1][2], S[t1][3] };
            float hv[8], lv[8];
#pragma unroll
            for (int e = 0; e < 8; e++) {
                __half hb = __float2half(pv[e]);
                hv[e] = __half2float(hb);
                lv[e] = pv[e] - hv[e];
            }
            pah[ks2][0] = pack_f16(hv[0], hv[1]); pah[ks2][1] = pack_f16(hv[2], hv[3]);
            pah[ks2][2] = pack_f16(hv[4], hv[5]); pah[ks2][3] = pack_f16(hv[6], hv[7]);
            pal[ks2][0] = pack_f16(lv[0], lv[1]); pal[ks2][1] = pack_f16(lv[2], lv[3]);
            pal[ks2][2] = pack_f16(lv[4], lv[5]); pal[ks2][3] = pack_f16(lv[6], lv[7]);
        }

#pragma unroll
        for (int ks2 = 0; ks2 < 2; ks2++) {
            const uint32_t vb = sb + FV(buf) + vOff + (uint32_t)ks2 * 16 * FROWB;
#pragma unroll
            for (int g16 = 0; g16 < 16; g16++) {
                uint32_t v[4];
                ldsm4t(v[0], v[1], v[2], v[3], vb + g16 * 32);
                const int n0 = g16 * 2, n1 = n0 + 1;
                mmah(o[n0], pah[ks2], v[0], v[1]);
                mmah(o[n0], pal[ks2], v[0], v[1]);
                mmah(o[n1], pah[ks2], v[2], v[3]);
                mmah(o[n1], pal[ks2], v[2], v[3]);
            }
        }
        __syncthreads();
    }

    l0 += __shfl_xor_sync(0xffffffffu, l0, 1);
    l0 += __shfl_xor_sync(0xffffffffu, l0, 2);
    l1 += __shfl_xor_sync(0xffffffffu, l1, 1);
    l1 += __shfl_xor_sync(0xffffffffu, l1, 2);
    const float inv0 = frcp(l0), inv1 = frcp(l1);

#pragma unroll
    for (int nt = 0; nt < 32; nt++) {
#pragma unroll
        for (int e = 0; e < 4; e++) {
            const int row = qbase + g + (e >> 1) * 8;
            const int d   = nt * 8 + cb + (e & 1);
            const size_t tq = (size_t)(b * 2048 + row);
            const float gt  = __half2float(P16[tq * SPLITC + 512 + h * HDIM + d]);
            const float sig = frcp(1.f + ex2(-gt * 1.4426950f));
            const float val = o[nt][e] * ((e < 2) ? inv0 : inv1) * sig;
            Attn[tq * QDIM + h * HDIM + d] = __float2half(val);
        }
    }
#undef KV_LOAD
}

// ---------------- launcher ------------------------------------------------------
extern "C" void kernel_launch(void* const* d_in, const int* in_sizes, int n_in,
                              void* d_out, int out_size)
{
    const float* hidden = (const float*)d_in[0];
    const float* cosb   = (const float*)d_in[1];
    const float* sinb   = (const float*)d_in[2];
    const float* Wq     = (const float*)d_in[3];
    const float* Wk     = (const float*)d_in[4];
    const float* Wv     = (const float*)d_in[5];
    const float* Wo     = (const float*)d_in[6];
    const float* qnw    = (const float*)d_in[7];
    const float* knw    = (const float*)d_in[8];
    float* out = (float*)d_out;

    __half *hidF, *Wcat, *WoF, *P16, *Qf, *KH, *KL, *Attn;
    float *P32;
    cudaGetSymbolAddress((void**)&hidF, g_hidF);
    cudaGetSymbolAddress((void**)&Wcat, g_Wcat);
    cudaGetSymbolAddress((void**)&WoF,  g_WoF);
    cudaGetSymbolAddress((void**)&P32,  g_P32);
    cudaGetSymbolAddress((void**)&P16,  g_P16);
    cudaGetSymbolAddress((void**)&Qf,   g_Qf);
    cudaGetSymbolAddress((void**)&KH,   g_KH);
    cudaGetSymbolAddress((void**)&KL,   g_KL);
    cudaGetSymbolAddress((void**)&Attn, g_Attn);

    cudaFuncSetAttribute(gemm_1t,   cudaFuncAttributeMaxDynamicSharedMemorySize, GSMEM1);
    cudaFuncSetAttribute(flash_f16, cudaFuncAttributeMaxDynamicSharedMemorySize, FSMEM);

    // 0) conversions (all single fp16)
    {
        int n4 = TOKENS * HIDDEN_ / 4;
        conv_f16<<<(n4 + 255) / 256, 256>>>(hidden, hidF, n4);
        int nw = PROJ_N * (HIDDEN_ / 4);
        conv_wcat<<<(nw + 255) / 256, 256>>>(Wq, Wk, Wv, Wcat);
        n4 = HIDDEN_ * QDIM / 4;
        conv_f16<<<(n4 + 255) / 256, 256>>>(Wo, WoF, n4);
    }
    // 1) fused QKV+gate projection (1-term): P[4096,9216]
    gemm_1t<<<dim3(PROJ_N / 128, TOKENS / 128), 256, GSMEM1>>>(
        hidF, Wcat, P32, P16, HIDDEN_, SPLITC, SPLITC);
    // 2) RMSNorm + RoPE
    rmsnorm_rope_f16<<<dim3(TOKENS, NHEADS), 256>>>(P32, SPLITC, qnw, cosb, sinb,
                                                    Qf, nullptr, QDIM);
    rmsnorm_rope_f16<<<dim3(TOKENS, NKV), 256>>>(P32 + QDIM, SPLITC, knw, cosb, sinb,
                                                 KH, KL, KVDIM);
    // 3) flash attention + sigmoid gate
    flash_f16<<<dim3(2048 / 16, 4), 256, FSMEM>>>(Qf, KH, KL, P16, Attn);
    // 4) output projection (1-term): out[4096,2048]
    gemm_1t<<<dim3(HIDDEN_ / 128, TOKENS / 128), 256, GSMEM1>>>(
        Attn, WoF, out, nullptr, QDIM, HIDDEN_, HIDDEN_);
}